// round 2
// baseline (speedup 1.0000x reference)
#include <cuda_runtime.h>
#include <math.h>

#define NB   32
#define NQ   900
#define NMM  300
#define ND   256
#define NCLS 90
#define NNC  91
#define KB   5
#define NROW (NCLS*KB)      // 450 boundary rows per batch
#define NEGINF -1000000000.0f

// -------- scratch (device globals; no allocation allowed) --------
__device__ __align__(128) float g_matched[NB*NMM*ND];     // gathered matched embeddings (raw)
__device__ __align__(128) float g_minv[NB*NMM];           // 1/||matched||
__device__ __align__(128) float g_qinv[NB*NQ];            // 1/||obj||
__device__ __align__(128) int   g_ism[NB*NQ];             // is-matched mask per (b,q)
__device__ __align__(128) float g_sims[NB*NMM*NCLS];      // matched_n . protos
__device__ __align__(128) float g_pinv[NCLS];             // 1/||proto||
__device__ __align__(128) int   g_topi[NB*NROW];          // top-K_B indices per (b,c,k), -1 invalid
__device__ __align__(128) float g_bn[NB*NROW*ND];         // normalized boundary rows
__device__ __align__(128) float g_simbu[NB*NROW*NQ];      // sim_bu (masked)
__device__ __align__(128) float g_gbar[NB*NROW*ND];       // subgroup means
__device__ __align__(128) int   g_sgv[NB*NROW];           // sg_valid
__device__ __align__(128) float g_lseP[NCLS];
__device__ __align__(128) float g_lseneg[NCLS];
__device__ double g_acc[3];   // 0: sum fl, 1: count sg_valid, 2: sum cec terms

// -------- helpers --------
__device__ __forceinline__ float logaddexpf_(float a, float b) {
    float m = fmaxf(a, b);
    return m + log1pf(expf(-fabsf(a - b)));
}

// insert (v,id) into sorted-desc top-5, tie -> lower id first (jax top_k semantics)
__device__ __forceinline__ void ins5(float v, int id, float* vals, int* ids) {
    #pragma unroll
    for (int j = 0; j < 5; j++) {
        bool better = (v > vals[j]) || (v == vals[j] && id < ids[j]);
        if (better) {
            float tv = vals[j]; int ti = ids[j];
            vals[j] = v; ids[j] = id;
            v = tv; id = ti;
        }
    }
}

// -------- kernels --------
__global__ void init_kernel() {
    if (threadIdx.x < 3) g_acc[threadIdx.x] = 0.0;
}

// one warp per obj row: inv norm + clear is_m
__global__ void obj_norm_kernel(const float* __restrict__ obj) {
    int warp = (blockIdx.x * blockDim.x + threadIdx.x) >> 5;
    int lane = threadIdx.x & 31;
    if (warp >= NB*NQ) return;
    const float4* r4 = (const float4*)(obj + (size_t)warp * ND);
    float ss = 0.f;
    for (int t = lane; t < ND/4; t += 32) {
        float4 v = r4[t];
        ss += v.x*v.x + v.y*v.y + v.z*v.z + v.w*v.w;
    }
    #pragma unroll
    for (int o = 16; o; o >>= 1) ss += __shfl_xor_sync(0xffffffffu, ss, o);
    if (lane == 0) {
        g_qinv[warp] = 1.0f / fmaxf(sqrtf(ss), 1e-12f);
        g_ism[warp] = 0;
    }
}

// one warp per matched row: gather + inv norm + set is_m
__global__ void gather_kernel(const float* __restrict__ obj, const int* __restrict__ src) {
    int warp = (blockIdx.x * blockDim.x + threadIdx.x) >> 5;
    int lane = threadIdx.x & 31;
    if (warp >= NB*NMM) return;
    int b = warp / NMM;
    int idx = src[warp];
    const float4* r4 = (const float4*)(obj + ((size_t)b*NQ + idx) * ND);
    float4* o4 = (float4*)(g_matched + (size_t)warp * ND);
    float ss = 0.f;
    for (int t = lane; t < ND/4; t += 32) {
        float4 v = r4[t];
        o4[t] = v;
        ss += v.x*v.x + v.y*v.y + v.z*v.z + v.w*v.w;
    }
    #pragma unroll
    for (int o = 16; o; o >>= 1) ss += __shfl_xor_sync(0xffffffffu, ss, o);
    if (lane == 0) {
        g_minv[warp] = 1.0f / fmaxf(sqrtf(ss), 1e-12f);
        g_ism[b*NQ + idx] = 1;
    }
}

__global__ void pinv_kernel(const float* __restrict__ protos) {
    int c = blockIdx.x;
    int lane = threadIdx.x;
    const float4* r4 = (const float4*)(protos + (size_t)c * ND);
    float ss = 0.f;
    for (int t = lane; t < ND/4; t += 32) {
        float4 v = r4[t];
        ss += v.x*v.x + v.y*v.y + v.z*v.z + v.w*v.w;
    }
    #pragma unroll
    for (int o = 16; o; o >>= 1) ss += __shfl_xor_sync(0xffffffffu, ss, o);
    if (lane == 0) g_pinv[c] = 1.0f / fmaxf(sqrtf(ss), 1e-6f);
}

// sims[r, c] = minv[r] * (matched[r] . protos[c]) ; 16 rows per block
__global__ __launch_bounds__(256) void sims_kernel(const float* __restrict__ protos) {
    __shared__ __align__(16) float As[16*ND];
    __shared__ float sminv[16];
    int r0 = blockIdx.x * 16;
    int tid = threadIdx.x;
    float4* s4 = (float4*)As;
    const float4* gm4 = (const float4*)(g_matched + (size_t)r0 * ND);
    for (int i = tid; i < 16*ND/4; i += 256) s4[i] = gm4[i];
    if (tid < 16) sminv[tid] = g_minv[r0 + tid];
    __syncthreads();
    for (int o = tid; o < 16*NCLS; o += 256) {
        int r = o / NCLS;
        int c = o - r*NCLS;
        const float4* p4 = (const float4*)(protos + (size_t)c * ND);
        const float4* a4 = (const float4*)(As + r * ND);
        float acc = 0.f;
        #pragma unroll 8
        for (int t = 0; t < ND/4; t++) {
            float4 a = a4[t];
            float4 p = __ldg(p4 + t);
            acc += a.x*p.x + a.y*p.y + a.z*p.z + a.w*p.w;
        }
        g_sims[(size_t)(r0 + r)*NCLS + c] = acc * sminv[r];
    }
}

// per (b,c): top-5 of dist = 1 - sim over n with label==c
__global__ void topk_dists_kernel(const int* __restrict__ labels) {
    int bc = blockIdx.x;
    int b = bc / NCLS, c = bc - b*NCLS;
    int lane = threadIdx.x;
    float lv[5]; int li[5];
    #pragma unroll
    for (int j = 0; j < 5; j++) { lv[j] = -1e30f; li[j] = 0x7fffffff; }
    int cnt = 0;
    for (int n = lane; n < NMM; n += 32) {
        if (labels[b*NMM + n] == c) {
            cnt++;
            float dd = 1.0f - g_sims[(size_t)(b*NMM + n)*NCLS + c];
            ins5(dd, n, lv, li);
        }
    }
    #pragma unroll
    for (int o = 16; o; o >>= 1) cnt += __shfl_xor_sync(0xffffffffu, cnt, o);
    __shared__ float sv[160];
    __shared__ int   si[160];
    #pragma unroll
    for (int j = 0; j < 5; j++) { sv[lane*5 + j] = lv[j]; si[lane*5 + j] = li[j]; }
    __syncwarp();
    if (lane == 0) {
        float fv[5]; int fi[5];
        #pragma unroll
        for (int j = 0; j < 5; j++) { fv[j] = -1e30f; fi[j] = 0x7fffffff; }
        for (int t = 0; t < 160; t++)
            if (si[t] != 0x7fffffff) ins5(sv[t], si[t], fv, fi);
        #pragma unroll
        for (int k = 0; k < 5; k++)
            g_topi[(size_t)bc*KB + k] = (k < cnt) ? fi[k] : -1;
    }
}

// build normalized boundary row matrix (zeros for invalid slots)
__global__ void gather_bn_kernel() {
    int row = blockIdx.x;               // b*450 + c*5 + k
    int b = row / NROW;
    int ti = g_topi[row];
    int t = threadIdx.x;                // 64 threads -> one float4 each
    float4* o4 = (float4*)(g_bn + (size_t)row * ND);
    if (ti < 0) {
        o4[t] = make_float4(0.f, 0.f, 0.f, 0.f);
    } else {
        float inv = g_minv[b*NMM + ti];
        float4 v = ((const float4*)(g_matched + ((size_t)b*NMM + ti)*ND))[t];
        o4[t] = make_float4(v.x*inv, v.y*inv, v.z*inv, v.w*inv);
    }
}

// sim_bu = bn @ obj^T, scaled by qinv, masked by is_m. 128x128x8 SGEMM tiles.
__global__ __launch_bounds__(256) void simbu_gemm_kernel(const float* __restrict__ obj) {
    int b = blockIdx.z;
    int mB = blockIdx.y, nB = blockIdx.x;
    __shared__ float As[8][132];
    __shared__ float Bs[8][132];
    int tid = threadIdx.x;
    int tx = tid & 15, ty = tid >> 4;
    int lr = tid >> 1;
    int lk = (tid & 1) * 4;
    int am = mB*128 + lr;
    int bn = nB*128 + lr;
    const float* Abase = g_bn + (size_t)b * NROW * ND;
    const float* Bbase = obj  + (size_t)b * NQ   * ND;
    float acc[8][8];
    #pragma unroll
    for (int i = 0; i < 8; i++)
        #pragma unroll
        for (int j = 0; j < 8; j++) acc[i][j] = 0.f;

    for (int k0 = 0; k0 < ND; k0 += 8) {
        float4 av = make_float4(0,0,0,0), bv = make_float4(0,0,0,0);
        if (am < NROW) av = *(const float4*)(Abase + (size_t)am*ND + k0 + lk);
        if (bn < NQ)   bv = *(const float4*)(Bbase + (size_t)bn*ND + k0 + lk);
        As[lk+0][lr] = av.x; As[lk+1][lr] = av.y; As[lk+2][lr] = av.z; As[lk+3][lr] = av.w;
        Bs[lk+0][lr] = bv.x; Bs[lk+1][lr] = bv.y; Bs[lk+2][lr] = bv.z; Bs[lk+3][lr] = bv.w;
        __syncthreads();
        #pragma unroll
        for (int k = 0; k < 8; k++) {
            float a[8], bb[8];
            #pragma unroll
            for (int i = 0; i < 8; i++) a[i] = As[k][ty*8 + i];
            #pragma unroll
            for (int j = 0; j < 8; j++) bb[j] = Bs[k][tx*8 + j];
            #pragma unroll
            for (int i = 0; i < 8; i++)
                #pragma unroll
                for (int j = 0; j < 8; j++)
                    acc[i][j] = fmaf(a[i], bb[j], acc[i][j]);
        }
        __syncthreads();
    }

    int nBase = nB*128 + tx*8;
    int mBase = mB*128 + ty*8;
    float qv[8]; int mk[8];
    #pragma unroll
    for (int j = 0; j < 8; j++) {
        int n = nBase + j;
        if (n < NQ) { qv[j] = g_qinv[b*NQ + n]; mk[j] = g_ism[b*NQ + n]; }
        else        { qv[j] = 0.f; mk[j] = 1; }
    }
    #pragma unroll
    for (int i = 0; i < 8; i++) {
        int m = mBase + i;
        if (m < NROW) {
            float* orow = g_simbu + ((size_t)b*NROW + m) * NQ;
            #pragma unroll
            for (int j = 0; j < 8; j++) {
                int n = nBase + j;
                if (n < NQ) orow[n] = mk[j] ? NEGINF : acc[i][j] * qv[j];
            }
        }
    }
}

// per boundary row: top-5 over Q (values+indices), then g_bar + sg_valid
__global__ __launch_bounds__(128) void topk_gbar_kernel(const float* __restrict__ obj) {
    int row = blockIdx.x;               // b*450 + c*5 + k
    int b = row / NROW;
    int tid = threadIdx.x;
    int ti = g_topi[row];
    if (ti < 0) { if (tid == 0) g_sgv[row] = 0; return; }

    const float* srow = g_simbu + (size_t)row * NQ;
    float lv[5]; int lq[5];
    #pragma unroll
    for (int j = 0; j < 5; j++) { lv[j] = -1e30f; lq[j] = 0x7fffffff; }
    for (int q = tid; q < NQ; q += 128) ins5(srow[q], q, lv, lq);

    __shared__ float cval[128];
    __shared__ int   cq[128];
    __shared__ float stopv[5];
    __shared__ int   stopq[5];

    for (int r = 0; r < 5; r++) {
        cval[tid] = lv[0];
        cq[tid]   = lq[0];
        __syncthreads();
        for (int o = 64; o; o >>= 1) {
            if (tid < o) {
                float v2 = cval[tid+o]; int q2 = cq[tid+o];
                if (v2 > cval[tid] || (v2 == cval[tid] && q2 < cq[tid])) {
                    cval[tid] = v2; cq[tid] = q2;
                }
            }
            __syncthreads();
        }
        if (tid == 0) { stopv[r] = cval[0]; stopq[r] = cq[0]; }
        __syncthreads();
        if (lq[0] == stopq[r] && lv[0] == stopv[r]) {
            lv[0]=lv[1]; lq[0]=lq[1]; lv[1]=lv[2]; lq[1]=lq[2];
            lv[2]=lv[3]; lq[2]=lq[3]; lv[3]=lv[4]; lq[3]=lq[4];
            lv[4] = -1e30f; lq[4] = 0x7fffffff;
        }
        __syncthreads();
    }

    bool nb[5]; int W = 0;
    #pragma unroll
    for (int m = 0; m < 5; m++) { nb[m] = stopv[m] > 0.0f; W += nb[m] ? 1 : 0; }
    if (W == 0) { if (tid == 0) g_sgv[row] = 0; return; }
    if (tid == 0) g_sgv[row] = 1;

    float invw = 1.0f / (1.0f + (float)W);
    const float* mrow = g_matched + ((size_t)b*NMM + ti) * ND;
    float* grow = g_gbar + (size_t)row * ND;
    for (int d = tid; d < ND; d += 128) {
        float g = mrow[d];
        #pragma unroll
        for (int m = 0; m < 5; m++)
            if (nb[m]) g += obj[((size_t)b*NQ + stopq[m])*ND + d];
        grow[d] = g * invw;
    }
}

// focal loss over valid subgroups; 8 rows per block to amortize W_cls reads
__global__ __launch_bounds__(128) void focal_kernel(const float* __restrict__ Wc,
                                                    const float* __restrict__ bc) {
    int r0 = blockIdx.x * 8;
    int tid = threadIdx.x;
    __shared__ __align__(16) float4 gb4[8][ND/4];
    __shared__ int flags[8];
    if (tid < 8) flags[tid] = g_sgv[r0 + tid];
    for (int t = tid; t < 8*(ND/4); t += 128) {
        int rr = t >> 6, tt = t & 63;
        gb4[rr][tt] = ((const float4*)(g_gbar + (size_t)(r0+rr)*ND))[tt];
    }
    __syncthreads();
    int nv = flags[0]+flags[1]+flags[2]+flags[3]+flags[4]+flags[5]+flags[6]+flags[7];
    if (nv == 0) return;

    float fsum = 0.f;
    if (tid < NNC) {
        float xs[8];
        float bias = bc[tid];
        #pragma unroll
        for (int rr = 0; rr < 8; rr++) xs[rr] = bias;
        const float4* w4 = (const float4*)(Wc + (size_t)tid * ND);
        for (int t = 0; t < ND/4; t++) {
            float4 w = __ldg(w4 + t);
            #pragma unroll
            for (int rr = 0; rr < 8; rr++) {
                float4 g = gb4[rr][t];
                xs[rr] += w.x*g.x + w.y*g.y + w.z*g.z + w.w*g.w;
            }
        }
        #pragma unroll
        for (int rr = 0; rr < 8; rr++) {
            if (!flags[rr]) continue;
            float x = xs[rr];
            float fl;
            if (tid == NNC - 1) {
                // t=1: 0.25 * softplus(-x) * sigmoid(-x)^2
                float sp = (x < 0.f) ? (-x + log1pf(expf(x))) : log1pf(expf(-x));
                float sn = 1.f / (1.f + expf(x));
                fl = 0.25f * sp * sn * sn;
            } else {
                // t=0: 0.75 * softplus(x) * sigmoid(x)^2
                float sp = (x > 0.f) ? (x + log1pf(expf(-x))) : log1pf(expf(x));
                float sg = 1.f / (1.f + expf(-x));
                fl = 0.75f * sp * sg * sg;
            }
            fsum += fl;
        }
    }
    __shared__ float red[128];
    red[tid] = fsum;
    __syncthreads();
    for (int o = 64; o; o >>= 1) { if (tid < o) red[tid] += red[tid+o]; __syncthreads(); }
    if (tid == 0) {
        atomicAdd(&g_acc[0], (double)(red[0] / 91.0f));
        atomicAdd(&g_acc[1], (double)nv);
    }
}

// column logsumexp of masked prototype-prototype similarities
__global__ void lseP_kernel(const float* __restrict__ protos) {
    int c = blockIdx.x;
    int tid = threadIdx.x;  // 128
    float val = -1e30f;
    if (tid < NCLS && tid != c) {
        const float4* a4 = (const float4*)(protos + (size_t)tid * ND);
        const float4* b4 = (const float4*)(protos + (size_t)c   * ND);
        float d = 0.f;
        for (int t = 0; t < ND/4; t++) {
            float4 a = __ldg(a4 + t), bb = __ldg(b4 + t);
            d += a.x*bb.x + a.y*bb.y + a.z*bb.z + a.w*bb.w;
        }
        val = d * g_pinv[tid] * g_pinv[c] / 0.1f;
    }
    __shared__ float sm[128];
    sm[tid] = val; __syncthreads();
    for (int o = 64; o; o >>= 1) { if (tid < o) sm[tid] = fmaxf(sm[tid], sm[tid+o]); __syncthreads(); }
    float mx = sm[0];
    __syncthreads();
    sm[tid] = (tid < NCLS && tid != c) ? expf(val - mx) : 0.f;
    __syncthreads();
    for (int o = 64; o; o >>= 1) { if (tid < o) sm[tid] += sm[tid+o]; __syncthreads(); }
    if (tid == 0) g_lseP[c] = mx + logf(sm[0]);
}

// column logsumexp of masked sample-prototype similarities + combine with lseP
__global__ void lseS_kernel(const int* __restrict__ labels) {
    int c = blockIdx.x;
    int tid = threadIdx.x;  // 256
    float pin = g_pinv[c];
    float m = -1e30f, s = 0.f;
    for (int i = tid; i < NB*NMM; i += 256) {
        if (labels[i] == c) continue;
        float v = g_sims[(size_t)i*NCLS + c] * pin / 0.1f;
        if (v > m) { s = s * expf(m - v) + 1.f; m = v; }
        else       { s += expf(v - m); }
    }
    __shared__ float sm[256], ss[256];
    sm[tid] = m; ss[tid] = s;
    __syncthreads();
    for (int o = 128; o; o >>= 1) {
        if (tid < o) {
            float m2 = sm[tid+o], s2 = ss[tid+o];
            float M = fmaxf(sm[tid], m2);
            ss[tid] = ss[tid]*expf(sm[tid]-M) + s2*expf(m2-M);
            sm[tid] = M;
        }
        __syncthreads();
    }
    if (tid == 0) {
        float lse = sm[0] + logf(ss[0]);
        g_lseneg[c] = logaddexpf_(lse, g_lseP[c]);
    }
}

__global__ void cec_kernel(const int* __restrict__ labels) {
    int i = blockIdx.x * 256 + threadIdx.x;
    float term = 0.f;
    if (i < NB*NMM) {
        int l = labels[i];
        float pos = g_sims[(size_t)i*NCLS + l] * g_pinv[l] / 0.1f;
        term = -pos + logaddexpf_(pos, g_lseneg[l]);
    }
    __shared__ float sm[256];
    sm[threadIdx.x] = term;
    __syncthreads();
    for (int o = 128; o; o >>= 1) { if (threadIdx.x < o) sm[threadIdx.x] += sm[threadIdx.x+o]; __syncthreads(); }
    if (threadIdx.x == 0) atomicAdd(&g_acc[2], (double)sm[0]);
}

__global__ void finalize_kernel(float* out) {
    double ns = g_acc[1] < 1.0 ? 1.0 : g_acc[1];
    out[0] = (float)(g_acc[0] / ns);
    out[1] = (float)(g_acc[2] / (double)(NB*NMM));
}

// -------- launch --------
extern "C" void kernel_launch(void* const* d_in, const int* in_sizes, int n_in,
                              void* d_out, int out_size) {
    const float* obj    = (const float*)d_in[0];
    const float* protos = (const float*)d_in[1];
    const float* Wc     = (const float*)d_in[2];
    const float* bc     = (const float*)d_in[3];
    const int*   src    = (const int*)d_in[4];
    const int*   labels = (const int*)d_in[5];
    float* out = (float*)d_out;

    init_kernel<<<1, 32>>>();
    obj_norm_kernel<<<(NB*NQ*32 + 255)/256, 256>>>(obj);
    gather_kernel<<<(NB*NMM*32 + 255)/256, 256>>>(obj, src);
    pinv_kernel<<<NCLS, 32>>>(protos);
    sims_kernel<<<(NB*NMM)/16, 256>>>(protos);
    topk_dists_kernel<<<NB*NCLS, 32>>>(labels);
    gather_bn_kernel<<<NB*NROW, 64>>>();
    {
        dim3 grid((NQ + 127)/128, (NROW + 127)/128, NB);
        simbu_gemm_kernel<<<grid, 256>>>(obj);
    }
    topk_gbar_kernel<<<NB*NROW, 128>>>(obj);
    focal_kernel<<<(NB*NROW)/8, 128>>>(Wc, bc);
    lseP_kernel<<<NCLS, 128>>>(protos);
    lseS_kernel<<<NCLS, 256>>>(labels);
    cec_kernel<<<(NB*NMM + 255)/256, 256>>>(labels);
    finalize_kernel<<<1, 1>>>(out);
}

// round 5
// speedup vs baseline: 1.0152x; 1.0152x over previous
#include <cuda_runtime.h>
#include <cuda_bf16.h>
#include <mma.h>
#include <cstdint>
#include <math.h>

using namespace nvcuda;

#define NB   32
#define NQ   900
#define NMM  300
#define ND   256
#define NCLS 90
#define NNC  91
#define KB   5
#define NROW (NCLS*KB)      // 450 boundary rows per batch
#define NEGINF -1000000000.0f

// -------- scratch (device globals; no allocation allowed) --------
__device__ __align__(128) float g_matched[NB*NMM*ND];     // gathered matched embeddings (raw)
__device__ __align__(128) float g_minv[NB*NMM];           // 1/||matched||
__device__ __align__(128) int   g_ism[NB*NQ];             // is-matched mask per (b,q)
__device__ __align__(128) float g_sims[NB*NMM*NCLS];      // matched_n . protos (fp32 exact)
__device__ __align__(128) float g_pinv[NCLS];             // 1/||proto||
__device__ __align__(128) int   g_topi[NB*NROW];          // top-K_B indices per (b,c,k), -1 invalid
__device__ __align__(128) __nv_bfloat16 g_Ah[NB*512*ND];  // boundary_n hi (padded to 512 rows)
__device__ __align__(128) __nv_bfloat16 g_Al[NB*512*ND];  // boundary_n lo
__device__ __align__(128) __nv_bfloat16 g_Bh[NB*NQ*ND];   // obj_n hi
__device__ __align__(128) __nv_bfloat16 g_Bl[NB*NQ*ND];   // obj_n lo
__device__ __align__(128) float g_pv[NB*NROW*8*KB];       // per-(row,nTile) top5 values
__device__ __align__(128) int   g_pq[NB*NROW*8*KB];       // per-(row,nTile) top5 q indices
__device__ __align__(128) float g_gbar[NB*NROW*ND];       // subgroup means
__device__ __align__(128) int   g_sgv[NB*NROW];           // sg_valid
__device__ __align__(128) float g_lseP[NCLS];
__device__ __align__(128) float g_lseneg[NCLS];
__device__ double g_acc[3];   // 0: sum fl, 1: count sg_valid, 2: sum cec terms

// -------- helpers --------
__device__ __forceinline__ float logaddexpf_(float a, float b) {
    float m = fmaxf(a, b);
    return m + log1pf(expf(-fabsf(a - b)));
}

// insert (v,id) into sorted-desc top-5, tie -> lower id first (jax top_k semantics)
__device__ __forceinline__ void ins5(float v, int id, float* vals, int* ids) {
    #pragma unroll
    for (int j = 0; j < 5; j++) {
        bool better = (v > vals[j]) || (v == vals[j] && id < ids[j]);
        if (better) {
            float tv = vals[j]; int ti = ids[j];
            vals[j] = v; ids[j] = id;
            v = tv; id = ti;
        }
    }
}

__device__ __forceinline__ void split_bf16(float a, unsigned short& h, unsigned short& l) {
    __nv_bfloat16 hb = __float2bfloat16(a);
    float hf = __bfloat162float(hb);
    __nv_bfloat16 lb = __float2bfloat16(a - hf);
    h = __bfloat16_as_ushort(hb);
    l = __bfloat16_as_ushort(lb);
}

// -------- kernels --------
__global__ void init_kernel() {
    if (threadIdx.x < 3) g_acc[threadIdx.x] = 0.0;
}

// one warp per obj row: normalize + bf16 hi/lo split + clear is_m
__global__ void pack_obj_kernel(const float* __restrict__ obj) {
    int warp = (blockIdx.x * blockDim.x + threadIdx.x) >> 5;
    int lane = threadIdx.x & 31;
    if (warp >= NB*NQ) return;
    const float4* r4 = (const float4*)(obj + (size_t)warp * ND);
    float4 a = r4[lane];
    float4 c = r4[lane + 32];
    float ss = a.x*a.x + a.y*a.y + a.z*a.z + a.w*a.w
             + c.x*c.x + c.y*c.y + c.z*c.z + c.w*c.w;
    #pragma unroll
    for (int o = 16; o; o >>= 1) ss += __shfl_xor_sync(0xffffffffu, ss, o);
    float inv = 1.0f / fmaxf(sqrtf(ss), 1e-12f);
    unsigned short h0,h1,h2,h3,l0,l1,l2,l3;
    uint2 hv, lv;
    split_bf16(a.x*inv,h0,l0); split_bf16(a.y*inv,h1,l1);
    split_bf16(a.z*inv,h2,l2); split_bf16(a.w*inv,h3,l3);
    hv.x = h0 | ((unsigned)h1<<16); hv.y = h2 | ((unsigned)h3<<16);
    lv.x = l0 | ((unsigned)l1<<16); lv.y = l2 | ((unsigned)l3<<16);
    ((uint2*)g_Bh)[(size_t)warp*64 + lane] = hv;
    ((uint2*)g_Bl)[(size_t)warp*64 + lane] = lv;
    split_bf16(c.x*inv,h0,l0); split_bf16(c.y*inv,h1,l1);
    split_bf16(c.z*inv,h2,l2); split_bf16(c.w*inv,h3,l3);
    hv.x = h0 | ((unsigned)h1<<16); hv.y = h2 | ((unsigned)h3<<16);
    lv.x = l0 | ((unsigned)l1<<16); lv.y = l2 | ((unsigned)l3<<16);
    ((uint2*)g_Bh)[(size_t)warp*64 + lane + 32] = hv;
    ((uint2*)g_Bl)[(size_t)warp*64 + lane + 32] = lv;
    if (lane == 0) g_ism[warp] = 0;
}

// one warp per matched row: gather + inv norm + set is_m
__global__ void gather_kernel(const float* __restrict__ obj, const int* __restrict__ src) {
    int warp = (blockIdx.x * blockDim.x + threadIdx.x) >> 5;
    int lane = threadIdx.x & 31;
    if (warp >= NB*NMM) return;
    int b = warp / NMM;
    int idx = src[warp];
    const float4* r4 = (const float4*)(obj + ((size_t)b*NQ + idx) * ND);
    float4* o4 = (float4*)(g_matched + (size_t)warp * ND);
    float ss = 0.f;
    for (int t = lane; t < ND/4; t += 32) {
        float4 v = r4[t];
        o4[t] = v;
        ss += v.x*v.x + v.y*v.y + v.z*v.z + v.w*v.w;
    }
    #pragma unroll
    for (int o = 16; o; o >>= 1) ss += __shfl_xor_sync(0xffffffffu, ss, o);
    if (lane == 0) {
        g_minv[warp] = 1.0f / fmaxf(sqrtf(ss), 1e-12f);
        g_ism[b*NQ + idx] = 1;
    }
}

__global__ void pinv_kernel(const float* __restrict__ protos) {
    int c = blockIdx.x;
    int lane = threadIdx.x;
    const float4* r4 = (const float4*)(protos + (size_t)c * ND);
    float ss = 0.f;
    for (int t = lane; t < ND/4; t += 32) {
        float4 v = r4[t];
        ss += v.x*v.x + v.y*v.y + v.z*v.z + v.w*v.w;
    }
    #pragma unroll
    for (int o = 16; o; o >>= 1) ss += __shfl_xor_sync(0xffffffffu, ss, o);
    if (lane == 0) g_pinv[c] = 1.0f / fmaxf(sqrtf(ss), 1e-6f);
}

// sims[r, c] = minv[r] * (matched[r] . protos[c]) ; 16 rows per block (fp32 exact)
__global__ __launch_bounds__(256) void sims_kernel(const float* __restrict__ protos) {
    __shared__ __align__(16) float As[16*ND];
    __shared__ float sminv[16];
    int r0 = blockIdx.x * 16;
    int tid = threadIdx.x;
    float4* s4 = (float4*)As;
    const float4* gm4 = (const float4*)(g_matched + (size_t)r0 * ND);
    for (int i = tid; i < 16*ND/4; i += 256) s4[i] = gm4[i];
    if (tid < 16) sminv[tid] = g_minv[r0 + tid];
    __syncthreads();
    for (int o = tid; o < 16*NCLS; o += 256) {
        int r = o / NCLS;
        int c = o - r*NCLS;
        const float4* p4 = (const float4*)(protos + (size_t)c * ND);
        const float4* a4 = (const float4*)(As + r * ND);
        float acc = 0.f;
        #pragma unroll 8
        for (int t = 0; t < ND/4; t++) {
            float4 a = a4[t];
            float4 p = __ldg(p4 + t);
            acc += a.x*p.x + a.y*p.y + a.z*p.z + a.w*p.w;
        }
        g_sims[(size_t)(r0 + r)*NCLS + c] = acc * sminv[r];
    }
}

// per (b,c): top-5 of dist = 1 - sim over n with label==c
__global__ void topk_dists_kernel(const int* __restrict__ labels) {
    int bc = blockIdx.x;
    int b = bc / NCLS, c = bc - b*NCLS;
    int lane = threadIdx.x;
    float lv[5]; int li[5];
    #pragma unroll
    for (int j = 0; j < 5; j++) { lv[j] = -1e30f; li[j] = 0x7fffffff; }
    int cnt = 0;
    for (int n = lane; n < NMM; n += 32) {
        if (labels[b*NMM + n] == c) {
            cnt++;
            float dd = 1.0f - g_sims[(size_t)(b*NMM + n)*NCLS + c];
            ins5(dd, n, lv, li);
        }
    }
    #pragma unroll
    for (int o = 16; o; o >>= 1) cnt += __shfl_xor_sync(0xffffffffu, cnt, o);
    __shared__ float sv[160];
    __shared__ int   si[160];
    #pragma unroll
    for (int j = 0; j < 5; j++) { sv[lane*5 + j] = lv[j]; si[lane*5 + j] = li[j]; }
    __syncwarp();
    if (lane == 0) {
        float fv[5]; int fi[5];
        #pragma unroll
        for (int j = 0; j < 5; j++) { fv[j] = -1e30f; fi[j] = 0x7fffffff; }
        for (int t = 0; t < 160; t++)
            if (si[t] != 0x7fffffff) ins5(sv[t], si[t], fv, fi);
        #pragma unroll
        for (int k = 0; k < 5; k++)
            g_topi[(size_t)bc*KB + k] = (k < cnt) ? fi[k] : -1;
    }
}

// build normalized boundary rows as bf16 hi/lo into 512-row padded matrix
__global__ void pack_bn_kernel() {
    int row = blockIdx.x;               // b*512 + r  over padded rows
    int b = row >> 9;                   // /512
    int r = row & 511;
    int t = threadIdx.x;                // 64 threads -> one float4 each
    uint2 hv = make_uint2(0,0), lv = make_uint2(0,0);
    if (r < NROW) {
        int ti = g_topi[b*NROW + r];
        if (ti >= 0) {
            float inv = g_minv[b*NMM + ti];
            float4 v = ((const float4*)(g_matched + ((size_t)b*NMM + ti)*ND))[t];
            unsigned short h0,h1,h2,h3,l0,l1,l2,l3;
            split_bf16(v.x*inv,h0,l0); split_bf16(v.y*inv,h1,l1);
            split_bf16(v.z*inv,h2,l2); split_bf16(v.w*inv,h3,l3);
            hv.x = h0 | ((unsigned)h1<<16); hv.y = h2 | ((unsigned)h3<<16);
            lv.x = l0 | ((unsigned)l1<<16); lv.y = l2 | ((unsigned)l3<<16);
        }
    }
    ((uint2*)g_Ah)[(size_t)row*64 + t] = hv;
    ((uint2*)g_Al)[(size_t)row*64 + t] = lv;
}

// sim_bu = bn_n @ obj_n^T via WMMA bf16, 3-term hi/lo compensation.
// Block: 128x128 tile, 8 warps, warp = 16 rows x 128 cols (owns complete rows).
// Fused per-row top-5 epilogue (partials per n-tile-of-128 merged later).
#define SLD 80   // smem leading dim (elements); 160B rows keep 32B fragment alignment
__global__ __launch_bounds__(256) void simbu_wmma_kernel() {
    __shared__ __align__(32) __nv_bfloat16 sA[128*SLD];
    __shared__ __align__(32) __nv_bfloat16 sB[128*SLD];
    __shared__ int smask[128];
    int tid = threadIdx.x, wid = tid >> 5, lane = tid & 31;
    int nT = blockIdx.x, mT = blockIdx.y, b = blockIdx.z;
    const int mBase = mT*128, nBase = nT*128;

    if (tid < 128) {
        int n = nBase + tid;
        smask[tid] = (n < NQ) ? g_ism[b*NQ + n] : 2;
    }

    wmma::fragment<wmma::accumulator, 16, 16, 16, float> acc[8];
    #pragma unroll
    for (int i = 0; i < 8; i++) wmma::fill_fragment(acc[i], 0.0f);

    // 12 K-chunks of 64: segments (Ah*Bh), (Al*Bh), (Ah*Bl)
    for (int chunk = 0; chunk < 12; chunk++) {
        int seg = chunk >> 2, kc = chunk & 3;
        const __nv_bfloat16* Asrc = (seg == 1) ? g_Al : g_Ah;
        const __nv_bfloat16* Bsrc = (seg == 2) ? g_Bl : g_Bh;
        __syncthreads();   // protect smem from prior iteration's readers
        #pragma unroll
        for (int i = 0; i < 4; i++) {
            int e = i*256 + tid;     // 0..1023
            int r = e >> 3;          // 0..127
            int cg = e & 7;          // 0..7 (8 bf16 each)
            uint4 bv = make_uint4(0,0,0,0);
            // A rows padded to 512 in gmem: no branch needed
            uint4 av = *(const uint4*)(Asrc + ((size_t)(b*512 + mBase + r)*ND + kc*64 + cg*8));
            int br = nBase + r;
            if (br < NQ) bv = *(const uint4*)(Bsrc + ((size_t)(b*NQ + br)*ND + kc*64 + cg*8));
            *(uint4*)(sA + r*SLD + cg*8) = av;
            *(uint4*)(sB + r*SLD + cg*8) = bv;
        }
        __syncthreads();
        #pragma unroll
        for (int ks = 0; ks < 4; ks++) {
            wmma::fragment<wmma::matrix_a, 16, 16, 16, __nv_bfloat16, wmma::row_major> af;
            wmma::load_matrix_sync(af, sA + (wid*16)*SLD + ks*16, SLD);
            #pragma unroll
            for (int nt = 0; nt < 8; nt++) {
                wmma::fragment<wmma::matrix_b, 16, 16, 16, __nv_bfloat16, wmma::col_major> bf;
                wmma::load_matrix_sync(bf, sB + (nt*16)*SLD + ks*16, SLD);
                wmma::mma_sync(acc[nt], af, bf, acc[nt]);
            }
        }
    }
    __syncthreads();   // all mma done reading sA/sB; safe to alias epilogue buffer

    // epilogue: per-warp 16x16 staging buffer aliased over sA
    float* ebuf = reinterpret_cast<float*>(sA) + (size_t)wid * 256;
    float tv[5]; int tq[5];
    #pragma unroll
    for (int j = 0; j < 5; j++) { tv[j] = -1e30f; tq[j] = 0x7fffffff; }
    #pragma unroll
    for (int nt = 0; nt < 8; nt++) {
        wmma::store_matrix_sync(ebuf, acc[nt], 16, wmma::mem_row_major);
        __syncwarp();
        if (lane < 16) {
            #pragma unroll
            for (int c = 0; c < 16; c++) {
                int col = nt*16 + c;
                int mk = smask[col];
                float v; int id;
                if (mk == 2)      { v = -1e30f; id = 0x7fffffff; }
                else if (mk == 1) { v = NEGINF; id = nBase + col; }
                else              { v = ebuf[lane*16 + c]; id = nBase + col; }
                ins5(v, id, tv, tq);
            }
        }
        __syncwarp();
    }
    if (lane < 16) {
        int m = mBase + wid*16 + lane;
        if (m < NROW) {
            size_t base = ((size_t)(b*NROW + m)*8 + nT)*5;
            #pragma unroll
            for (int j = 0; j < 5; j++) { g_pv[base+j] = tv[j]; g_pq[base+j] = tq[j]; }
        }
    }
}

// merge 8 partial top-5 lists per row -> final top-5, then g_bar + sg_valid.
// one warp per row, 8 rows per block
__global__ __launch_bounds__(256) void merge_gbar_kernel(const float* __restrict__ obj) {
    __shared__ float sv[8][40];
    __shared__ int   si[8][40];
    __shared__ int   bq[8][8];
    int w = threadIdx.x >> 5, lane = threadIdx.x & 31;
    int R = blockIdx.x*8 + w;
    int b = R / NROW;
    int ti = g_topi[R];
    if (ti < 0) { if (lane == 0) g_sgv[R] = 0; return; }
    size_t pbase = (size_t)R * 40;
    for (int j = lane; j < 40; j += 32) { sv[w][j] = g_pv[pbase+j]; si[w][j] = g_pq[pbase+j]; }
    __syncwarp();
    if (lane == 0) {
        float fv[5]; int fq[5];
        #pragma unroll
        for (int j = 0; j < 5; j++) { fv[j] = -1e30f; fq[j] = 0x7fffffff; }
        for (int j = 0; j < 40; j++) {
            float v = sv[w][j]; int id = si[w][j];
            if (!(v < fv[4])) ins5(v, id, fv, fq);
        }
        int W = 0;
        #pragma unroll
        for (int mm = 0; mm < 5; mm++) {
            bool nb = fv[mm] > 0.0f;
            bq[w][mm] = nb ? fq[mm] : -1;
            W += nb ? 1 : 0;
        }
        bq[w][5] = W;
    }
    __syncwarp();
    int W = bq[w][5];
    if (W == 0) { if (lane == 0) g_sgv[R] = 0; return; }
    if (lane == 0) g_sgv[R] = 1;
    float invw = 1.0f / (1.0f + (float)W);
    int d0 = lane * 8;
    const float* mrow = g_matched + ((size_t)b*NMM + ti)*ND + d0;
    float acc[8];
    #pragma unroll
    for (int e = 0; e < 8; e++) acc[e] = mrow[e];
    #pragma unroll
    for (int mm = 0; mm < 5; mm++) {
        int q = bq[w][mm];
        if (q >= 0) {
            const float* ur = obj + ((size_t)b*NQ + q)*ND + d0;
            #pragma unroll
            for (int e = 0; e < 8; e++) acc[e] += ur[e];
        }
    }
    float* gr = g_gbar + (size_t)R*ND + d0;
    #pragma unroll
    for (int e = 0; e < 8; e++) gr[e] = acc[e] * invw;
}

// focal loss over valid subgroups; 8 rows per block to amortize W_cls reads
__global__ __launch_bounds__(128) void focal_kernel(const float* __restrict__ Wc,
                                                    const float* __restrict__ bc) {
    int r0 = blockIdx.x * 8;
    int tid = threadIdx.x;
    __shared__ __align__(16) float4 gb4[8][ND/4];
    __shared__ int flags[8];
    if (tid < 8) flags[tid] = g_sgv[r0 + tid];
    for (int t = tid; t < 8*(ND/4); t += 128) {
        int rr = t >> 6, tt = t & 63;
        gb4[rr][tt] = ((const float4*)(g_gbar + (size_t)(r0+rr)*ND))[tt];
    }
    __syncthreads();
    int nv = flags[0]+flags[1]+flags[2]+flags[3]+flags[4]+flags[5]+flags[6]+flags[7];
    if (nv == 0) return;

    float fsum = 0.f;
    if (tid < NNC) {
        float xs[8];
        float bias = bc[tid];
        #pragma unroll
        for (int rr = 0; rr < 8; rr++) xs[rr] = bias;
        const float4* w4 = (const float4*)(Wc + (size_t)tid * ND);
        for (int t = 0; t < ND/4; t++) {
            float4 w = __ldg(w4 + t);
            #pragma unroll
            for (int rr = 0; rr < 8; rr++) {
                float4 g = gb4[rr][t];
                xs[rr] += w.x*g.x + w.y*g.y + w.z*g.z + w.w*g.w;
            }
        }
        #pragma unroll
        for (int rr = 0; rr < 8; rr++) {
            if (!flags[rr]) continue;
            float x = xs[rr];
            float fl;
            if (tid == NNC - 1) {
                float sp = (x < 0.f) ? (-x + log1pf(expf(x))) : log1pf(expf(-x));
                float sn = 1.f / (1.f + expf(x));
                fl = 0.25f * sp * sn * sn;
            } else {
                float sp = (x > 0.f) ? (x + log1pf(expf(-x))) : log1pf(expf(x));
                float sg = 1.f / (1.f + expf(-x));
                fl = 0.75f * sp * sg * sg;
            }
            fsum += fl;
        }
    }
    __shared__ float red[128];
    red[tid] = fsum;
    __syncthreads();
    for (int o = 64; o; o >>= 1) { if (tid < o) red[tid] += red[tid+o]; __syncthreads(); }
    if (tid == 0) {
        atomicAdd(&g_acc[0], (double)(red[0] / 91.0f));
        atomicAdd(&g_acc[1], (double)nv);
    }
}

// column logsumexp of masked prototype-prototype similarities
__global__ void lseP_kernel(const float* __restrict__ protos) {
    int c = blockIdx.x;
    int tid = threadIdx.x;  // 128
    float val = -1e30f;
    if (tid < NCLS && tid != c) {
        const float4* a4 = (const float4*)(protos + (size_t)tid * ND);
        const float4* b4 = (const float4*)(protos + (size_t)c   * ND);
        float d = 0.f;
        for (int t = 0; t < ND/4; t++) {
            float4 a = __ldg(a4 + t), bb = __ldg(b4 + t);
            d += a.x*bb.x + a.y*bb.y + a.z*bb.z + a.w*bb.w;
        }
        val = d * g_pinv[tid] * g_pinv[c] / 0.1f;
    }
    __shared__ float sm[128];
    sm[tid] = val; __syncthreads();
    for (int o = 64; o; o >>= 1) { if (tid < o) sm[tid] = fmaxf(sm[tid], sm[tid+o]); __syncthreads(); }
    float mx = sm[0];
    __syncthreads();
    sm[tid] = (tid < NCLS && tid != c) ? expf(val - mx) : 0.f;
    __syncthreads();
    for (int o = 64; o; o >>= 1) { if (tid < o) sm[tid] += sm[tid+o]; __syncthreads(); }
    if (tid == 0) g_lseP[c] = mx + logf(sm[0]);
}

// column logsumexp of masked sample-prototype similarities + combine with lseP
__global__ void lseS_kernel(const int* __restrict__ labels) {
    int c = blockIdx.x;
    int tid = threadIdx.x;  // 256
    float pin = g_pinv[c];
    float m = -1e30f, s = 0.f;
    for (int i = tid; i < NB*NMM; i += 256) {
        if (labels[i] == c) continue;
        float v = g_sims[(size_t)i*NCLS + c] * pin / 0.1f;
        if (v > m) { s = s * expf(m - v) + 1.f; m = v; }
        else       { s += expf(v - m); }
    }
    __shared__ float sm[256], ss[256];
    sm[tid] = m; ss[tid] = s;
    __syncthreads();
    for (int o = 128; o; o >>= 1) {
        if (tid < o) {
            float m2 = sm[tid+o], s2 = ss[tid+o];
            float M = fmaxf(sm[tid], m2);
            ss[tid] = ss[tid]*expf(sm[tid]-M) + s2*expf(m2-M);
            sm[tid] = M;
        }
        __syncthreads();
    }
    if (tid == 0) {
        float lse = sm[0] + logf(ss[0]);
        g_lseneg[c] = logaddexpf_(lse, g_lseP[c]);
    }
}

__global__ void cec_kernel(const int* __restrict__ labels) {
    int i = blockIdx.x * 256 + threadIdx.x;
    float term = 0.f;
    if (i < NB*NMM) {
        int l = labels[i];
        float pos = g_sims[(size_t)i*NCLS + l] * g_pinv[l] / 0.1f;
        term = -pos + logaddexpf_(pos, g_lseneg[l]);
    }
    __shared__ float sm[256];
    sm[threadIdx.x] = term;
    __syncthreads();
    for (int o = 128; o; o >>= 1) { if (threadIdx.x < o) sm[threadIdx.x] += sm[threadIdx.x+o]; __syncthreads(); }
    if (threadIdx.x == 0) atomicAdd(&g_acc[2], (double)sm[0]);
}

__global__ void finalize_kernel(float* out) {
    double ns = g_acc[1] < 1.0 ? 1.0 : g_acc[1];
    out[0] = (float)(g_acc[0] / ns);
    out[1] = (float)(g_acc[2] / (double)(NB*NMM));
}

// -------- launch --------
extern "C" void kernel_launch(void* const* d_in, const int* in_sizes, int n_in,
                              void* d_out, int out_size) {
    const float* obj    = (const float*)d_in[0];
    const float* protos = (const float*)d_in[1];
    const float* Wc     = (const float*)d_in[2];
    const float* bc     = (const float*)d_in[3];
    const int*   src    = (const int*)d_in[4];
    const int*   labels = (const int*)d_in[5];
    float* out = (float*)d_out;

    init_kernel<<<1, 32>>>();
    pack_obj_kernel<<<(NB*NQ*32 + 255)/256, 256>>>(obj);
    gather_kernel<<<(NB*NMM*32 + 255)/256, 256>>>(obj, src);
    pinv_kernel<<<NCLS, 32>>>(protos);
    sims_kernel<<<(NB*NMM)/16, 256>>>(protos);
    topk_dists_kernel<<<NB*NCLS, 32>>>(labels);
    pack_bn_kernel<<<NB*512, 64>>>();
    {
        dim3 grid(8, 4, NB);   // nTiles(1024/128) x mTiles(512/128) x batch
        simbu_wmma_kernel<<<grid, 256>>>();
    }
    merge_gbar_kernel<<<(NB*NROW)/8, 256>>>(obj);
    focal_kernel<<<(NB*NROW)/8, 128>>>(Wc, bc);
    lseP_kernel<<<NCLS, 128>>>(protos);
    lseS_kernel<<<NCLS, 256>>>(labels);
    cec_kernel<<<(NB*NMM + 255)/256, 256>>>(labels);
    finalize_kernel<<<1, 1>>>(out);
}

// round 6
// speedup vs baseline: 1.2699x; 1.2509x over previous
#include <cuda_runtime.h>
#include <cuda_bf16.h>
#include <mma.h>
#include <cstdint>
#include <math.h>

using namespace nvcuda;

#define NB   32
#define NQ   900
#define NMM  300
#define MPAD 384            // matched rows padded for 128-tiles
#define ND   256
#define NCLS 90
#define NNC  91
#define KB   5
#define NROW (NCLS*KB)      // 450 boundary rows per batch
#define NEGINF -1000000000.0f
#define SLD  72             // smem leading dim (bf16 elements), 144B rows: conflict-free LDSM
#define TILEB 18432u        // 128*72*2 bytes per tile

// -------- scratch (device globals; no allocation allowed) --------
__device__ __align__(128) float g_matched[NB*NMM*ND];     // gathered matched embeddings (raw)
__device__ __align__(128) float g_minv[NB*NMM];           // 1/||matched||
__device__ __align__(128) int   g_ism[NB*NQ];             // is-matched mask per (b,q)
__device__ __align__(128) float g_sims[NB*NMM*NCLS];      // matched_n . protos (fp32 exact)
__device__ __align__(128) float g_pinv[NCLS];             // 1/||proto||
__device__ __align__(128) int   g_topi[NB*NROW];          // top-K_B indices per (b,c,k), -1 invalid
__device__ __align__(128) __nv_bfloat16 g_Mh[NB*MPAD*ND]; // matched_n hi (padded rows zero)
__device__ __align__(128) __nv_bfloat16 g_Ml[NB*MPAD*ND]; // matched_n lo
__device__ __align__(128) __nv_bfloat16 g_Bh[NB*NQ*ND];   // obj_n hi
__device__ __align__(128) __nv_bfloat16 g_Bl[NB*NQ*ND];   // obj_n lo
__device__ __align__(128) float g_pv[NB*NMM*8*KB];        // per-(matched row,nTile) top5 values
__device__ __align__(128) int   g_pq[NB*NMM*8*KB];        // per-(matched row,nTile) top5 q indices
__device__ __align__(128) float g_gbar[NB*NROW*ND];       // subgroup means
__device__ __align__(128) int   g_sgv[NB*NROW];           // sg_valid
__device__ __align__(128) float g_lseP[NCLS];
__device__ __align__(128) float g_lseneg[NCLS];
__device__ double g_acc[3];   // 0: sum fl, 1: count sg_valid, 2: sum cec terms

// -------- helpers --------
__device__ __forceinline__ float logaddexpf_(float a, float b) {
    float m = fmaxf(a, b);
    return m + log1pf(expf(-fabsf(a - b)));
}

// insert (v,id) into sorted-desc top-5, tie -> lower id first (jax top_k semantics)
__device__ __forceinline__ void ins5(float v, int id, float* vals, int* ids) {
    #pragma unroll
    for (int j = 0; j < 5; j++) {
        bool better = (v > vals[j]) || (v == vals[j] && id < ids[j]);
        if (better) {
            float tv = vals[j]; int ti = ids[j];
            vals[j] = v; ids[j] = id;
            v = tv; id = ti;
        }
    }
}

__device__ __forceinline__ void split_bf16(float a, unsigned short& h, unsigned short& l) {
    __nv_bfloat16 hb = __float2bfloat16(a);
    float hf = __bfloat162float(hb);
    __nv_bfloat16 lb = __float2bfloat16(a - hf);
    h = __bfloat16_as_ushort(hb);
    l = __bfloat16_as_ushort(lb);
}

__device__ __forceinline__ void cp16(uint32_t s, const void* g) {
    asm volatile("cp.async.ca.shared.global [%0], [%1], 16;" :: "r"(s), "l"(g));
}
__device__ __forceinline__ void cp16z(uint32_t s, const void* g, int sz) {
    asm volatile("cp.async.ca.shared.global [%0], [%1], 16, %2;" :: "r"(s), "l"(g), "r"(sz));
}

// -------- kernels --------

// launch 1: one warp per obj row: normalize + bf16 hi/lo split + clear is_m (+ zero g_acc)
__global__ void pack_obj_kernel(const float* __restrict__ obj) {
    if (blockIdx.x == 0 && threadIdx.x < 3) g_acc[threadIdx.x] = 0.0;
    int warp = (blockIdx.x * blockDim.x + threadIdx.x) >> 5;
    int lane = threadIdx.x & 31;
    if (warp >= NB*NQ) return;
    const float4* r4 = (const float4*)(obj + (size_t)warp * ND);
    float4 a = r4[lane];
    float4 c = r4[lane + 32];
    float ss = a.x*a.x + a.y*a.y + a.z*a.z + a.w*a.w
             + c.x*c.x + c.y*c.y + c.z*c.z + c.w*c.w;
    #pragma unroll
    for (int o = 16; o; o >>= 1) ss += __shfl_xor_sync(0xffffffffu, ss, o);
    float inv = 1.0f / fmaxf(sqrtf(ss), 1e-12f);
    unsigned short h0,h1,h2,h3,l0,l1,l2,l3;
    uint2 hv, lv;
    split_bf16(a.x*inv,h0,l0); split_bf16(a.y*inv,h1,l1);
    split_bf16(a.z*inv,h2,l2); split_bf16(a.w*inv,h3,l3);
    hv.x = h0 | ((unsigned)h1<<16); hv.y = h2 | ((unsigned)h3<<16);
    lv.x = l0 | ((unsigned)l1<<16); lv.y = l2 | ((unsigned)l3<<16);
    ((uint2*)g_Bh)[(size_t)warp*64 + lane] = hv;
    ((uint2*)g_Bl)[(size_t)warp*64 + lane] = lv;
    split_bf16(c.x*inv,h0,l0); split_bf16(c.y*inv,h1,l1);
    split_bf16(c.z*inv,h2,l2); split_bf16(c.w*inv,h3,l3);
    hv.x = h0 | ((unsigned)h1<<16); hv.y = h2 | ((unsigned)h3<<16);
    lv.x = l0 | ((unsigned)l1<<16); lv.y = l2 | ((unsigned)l3<<16);
    ((uint2*)g_Bh)[(size_t)warp*64 + lane + 32] = hv;
    ((uint2*)g_Bl)[(size_t)warp*64 + lane + 32] = lv;
    if (lane == 0) g_ism[warp] = 0;
}

// launch 2: one warp per padded matched row: gather + norm + is_m + fp32 copy + bf16 hi/lo
__global__ void gather_pack_kernel(const float* __restrict__ obj, const int* __restrict__ src) {
    int warp = (blockIdx.x * blockDim.x + threadIdx.x) >> 5;
    int lane = threadIdx.x & 31;
    if (warp >= NB*MPAD) return;
    int b = warp / MPAD, n = warp - b*MPAD;
    size_t mrow = (size_t)b*MPAD + n;
    if (n >= NMM) {
        uint2 z = make_uint2(0,0);
        ((uint2*)g_Mh)[mrow*64 + lane] = z;
        ((uint2*)g_Mh)[mrow*64 + lane + 32] = z;
        ((uint2*)g_Ml)[mrow*64 + lane] = z;
        ((uint2*)g_Ml)[mrow*64 + lane + 32] = z;
        return;
    }
    int idx = src[b*NMM + n];
    const float4* r4 = (const float4*)(obj + ((size_t)b*NQ + idx) * ND);
    float4 a = r4[lane];
    float4 c = r4[lane + 32];
    float4* o4 = (float4*)(g_matched + ((size_t)b*NMM + n) * ND);
    o4[lane] = a; o4[lane + 32] = c;
    float ss = a.x*a.x + a.y*a.y + a.z*a.z + a.w*a.w
             + c.x*c.x + c.y*c.y + c.z*c.z + c.w*c.w;
    #pragma unroll
    for (int o = 16; o; o >>= 1) ss += __shfl_xor_sync(0xffffffffu, ss, o);
    float inv = 1.0f / fmaxf(sqrtf(ss), 1e-12f);
    unsigned short h0,h1,h2,h3,l0,l1,l2,l3;
    uint2 hv, lv;
    split_bf16(a.x*inv,h0,l0); split_bf16(a.y*inv,h1,l1);
    split_bf16(a.z*inv,h2,l2); split_bf16(a.w*inv,h3,l3);
    hv.x = h0 | ((unsigned)h1<<16); hv.y = h2 | ((unsigned)h3<<16);
    lv.x = l0 | ((unsigned)l1<<16); lv.y = l2 | ((unsigned)l3<<16);
    ((uint2*)g_Mh)[mrow*64 + lane] = hv;
    ((uint2*)g_Ml)[mrow*64 + lane] = lv;
    split_bf16(c.x*inv,h0,l0); split_bf16(c.y*inv,h1,l1);
    split_bf16(c.z*inv,h2,l2); split_bf16(c.w*inv,h3,l3);
    hv.x = h0 | ((unsigned)h1<<16); hv.y = h2 | ((unsigned)h3<<16);
    lv.x = l0 | ((unsigned)l1<<16); lv.y = l2 | ((unsigned)l3<<16);
    ((uint2*)g_Mh)[mrow*64 + lane + 32] = hv;
    ((uint2*)g_Ml)[mrow*64 + lane + 32] = lv;
    if (lane == 0) {
        g_minv[b*NMM + n] = inv;
        g_ism[b*NQ + idx] = 1;
    }
}

// launch 3: sims[r, c] = minv[r] * (matched[r] . protos[c]) ; 16 rows per block (fp32 exact)
__global__ __launch_bounds__(256) void sims_kernel(const float* __restrict__ protos) {
    __shared__ __align__(16) float As[16*ND];
    __shared__ float sminv[16];
    int r0 = blockIdx.x * 16;
    int tid = threadIdx.x;
    float4* s4 = (float4*)As;
    const float4* gm4 = (const float4*)(g_matched + (size_t)r0 * ND);
    for (int i = tid; i < 16*ND/4; i += 256) s4[i] = gm4[i];
    if (tid < 16) sminv[tid] = g_minv[r0 + tid];
    __syncthreads();
    for (int o = tid; o < 16*NCLS; o += 256) {
        int r = o / NCLS;
        int c = o - r*NCLS;
        const float4* p4 = (const float4*)(protos + (size_t)c * ND);
        const float4* a4 = (const float4*)(As + r * ND);
        float acc = 0.f;
        #pragma unroll 8
        for (int t = 0; t < ND/4; t++) {
            float4 a = a4[t];
            float4 p = __ldg(p4 + t);
            acc += a.x*p.x + a.y*p.y + a.z*p.z + a.w*p.w;
        }
        g_sims[(size_t)(r0 + r)*NCLS + c] = acc * sminv[r];
    }
}

// launch 4 (PROFILED SLOT): S = matched_n @ obj_n^T via WMMA bf16 3-term hi/lo,
// cp.async double-buffered, fused per-row-per-ntile top-5 epilogue.
__global__ __launch_bounds__(256) void simbu_wmma_kernel() {
    extern __shared__ __align__(16) char dsm[];   // 4 tiles of TILEB: [A0,B0,A1,B1]
    __shared__ int smask[128];
    int tid = threadIdx.x, wid = tid >> 5, lane = tid & 31;
    int nT = blockIdx.x, mT = blockIdx.y, b = blockIdx.z;
    const int mBase = mT*128, nBase = nT*128;
    uint32_t sbase = (uint32_t)__cvta_generic_to_shared(dsm);

    if (tid < 128) {
        int n = nBase + tid;
        smask[tid] = (n < NQ) ? g_ism[b*NQ + n] : 2;
    }

    wmma::fragment<wmma::accumulator, 16, 16, 16, float> acc[8];
    #pragma unroll
    for (int i = 0; i < 8; i++) wmma::fill_fragment(acc[i], 0.0f);

    // chunk = seg*4 + kc; segments: 0:(Mh,Bh) 1:(Ml,Bh) 2:(Mh,Bl); K-chunk = 64 bf16
    #define ISSUE_CHUNK(chunk) do {                                                   \
        int seg_ = (chunk) >> 2, kc_ = (chunk) & 3, bi_ = (chunk) & 1;                \
        const __nv_bfloat16* Asrc_ = (seg_ == 1) ? g_Ml : g_Mh;                       \
        const __nv_bfloat16* Bsrc_ = (seg_ == 2) ? g_Bl : g_Bh;                       \
        uint32_t sa_ = sbase + (uint32_t)bi_ * (2u*TILEB);                            \
        uint32_t sb_ = sa_ + TILEB;                                                   \
        _Pragma("unroll")                                                             \
        for (int i_ = 0; i_ < 2; i_++) {                                              \
            int e_ = i_*256 + tid;                                                    \
            int r_ = e_ >> 2, g_ = e_ & 3;                                            \
            cp16(sa_ + (uint32_t)(r_*144 + g_*16),                                    \
                 Asrc_ + ((size_t)(b*MPAD + mBase + r_)*ND + kc_*64 + g_*8));         \
            int br_ = nBase + r_;                                                     \
            cp16z(sb_ + (uint32_t)(r_*144 + g_*16),                                   \
                  Bsrc_ + ((size_t)b*NQ + (br_ < NQ ? br_ : 0))*ND + kc_*64 + g_*8,   \
                  (br_ < NQ) ? 16 : 0);                                               \
        }                                                                             \
        asm volatile("cp.async.commit_group;" ::: "memory");                          \
    } while (0)

    ISSUE_CHUNK(0);
    for (int c = 0; c < 12; c++) {
        if (c + 1 < 12) {
            ISSUE_CHUNK(c + 1);
            asm volatile("cp.async.wait_group 1;" ::: "memory");
        } else {
            asm volatile("cp.async.wait_group 0;" ::: "memory");
        }
        __syncthreads();
        int bi = c & 1;
        const __nv_bfloat16* Ab = (const __nv_bfloat16*)(dsm + (size_t)bi*(2*TILEB));
        const __nv_bfloat16* Bb = (const __nv_bfloat16*)(dsm + (size_t)bi*(2*TILEB) + TILEB);
        #pragma unroll
        for (int ks = 0; ks < 4; ks++) {
            wmma::fragment<wmma::matrix_a, 16, 16, 16, __nv_bfloat16, wmma::row_major> af;
            wmma::load_matrix_sync(af, Ab + (wid*16)*SLD + ks*16, SLD);
            #pragma unroll
            for (int nt = 0; nt < 8; nt++) {
                wmma::fragment<wmma::matrix_b, 16, 16, 16, __nv_bfloat16, wmma::col_major> bf;
                wmma::load_matrix_sync(bf, Bb + (nt*16)*SLD + ks*16, SLD);
                wmma::mma_sync(acc[nt], af, bf, acc[nt]);
            }
        }
        __syncthreads();
    }
    #undef ISSUE_CHUNK

    // epilogue: per-warp 16x20 f32 staging buffer aliased over buffer 0
    float* ebuf = reinterpret_cast<float*>(dsm) + (size_t)wid * 320;
    float tv[5]; int tq[5];
    #pragma unroll
    for (int j = 0; j < 5; j++) { tv[j] = -1e30f; tq[j] = 0x7fffffff; }
    #pragma unroll
    for (int nt = 0; nt < 8; nt++) {
        wmma::store_matrix_sync(ebuf, acc[nt], 20, wmma::mem_row_major);
        __syncwarp();
        if (lane < 16) {
            #pragma unroll
            for (int cc = 0; cc < 16; cc++) {
                int col = nt*16 + cc;
                int mk = smask[col];
                float v; int id;
                if (mk == 2)      { v = -1e30f; id = 0x7fffffff; }
                else if (mk == 1) { v = NEGINF; id = nBase + col; }
                else              { v = ebuf[lane*20 + cc]; id = nBase + col; }
                ins5(v, id, tv, tq);
            }
        }
        __syncwarp();
    }
    if (lane < 16) {
        int m = mBase + wid*16 + lane;
        if (m < NMM) {
            size_t base = ((size_t)(b*NMM + m)*8 + nT)*5;
            #pragma unroll
            for (int j = 0; j < 5; j++) { g_pv[base+j] = tv[j]; g_pq[base+j] = tq[j]; }
        }
    }
}

// launch 5: per (b,c): top-5 of dist = 1 - sim over n with label==c
__global__ void topk_dists_kernel(const int* __restrict__ labels) {
    int bc = blockIdx.x;
    int b = bc / NCLS, c = bc - b*NCLS;
    int lane = threadIdx.x;
    float lv[5]; int li[5];
    #pragma unroll
    for (int j = 0; j < 5; j++) { lv[j] = -1e30f; li[j] = 0x7fffffff; }
    int cnt = 0;
    for (int n = lane; n < NMM; n += 32) {
        if (labels[b*NMM + n] == c) {
            cnt++;
            float dd = 1.0f - g_sims[(size_t)(b*NMM + n)*NCLS + c];
            ins5(dd, n, lv, li);
        }
    }
    #pragma unroll
    for (int o = 16; o; o >>= 1) cnt += __shfl_xor_sync(0xffffffffu, cnt, o);
    __shared__ float sv[160];
    __shared__ int   si[160];
    #pragma unroll
    for (int j = 0; j < 5; j++) { sv[lane*5 + j] = lv[j]; si[lane*5 + j] = li[j]; }
    __syncwarp();
    if (lane == 0) {
        float fv[5]; int fi[5];
        #pragma unroll
        for (int j = 0; j < 5; j++) { fv[j] = -1e30f; fi[j] = 0x7fffffff; }
        for (int t = 0; t < 160; t++)
            if (si[t] != 0x7fffffff) ins5(sv[t], si[t], fv, fi);
        #pragma unroll
        for (int k = 0; k < 5; k++)
            g_topi[(size_t)bc*KB + k] = (k < cnt) ? fi[k] : -1;
    }
}

// launch 6
__global__ void pinv_kernel(const float* __restrict__ protos) {
    int c = blockIdx.x;
    int lane = threadIdx.x;
    const float4* r4 = (const float4*)(protos + (size_t)c * ND);
    float ss = 0.f;
    for (int t = lane; t < ND/4; t += 32) {
        float4 v = r4[t];
        ss += v.x*v.x + v.y*v.y + v.z*v.z + v.w*v.w;
    }
    #pragma unroll
    for (int o = 16; o; o >>= 1) ss += __shfl_xor_sync(0xffffffffu, ss, o);
    if (lane == 0) g_pinv[c] = 1.0f / fmaxf(sqrtf(ss), 1e-6f);
}

// launch 7: per boundary row: look up ti's 40 partial candidates -> top-5 -> g_bar + sg_valid
__global__ __launch_bounds__(256) void merge_gbar_kernel(const float* __restrict__ obj) {
    __shared__ float sv[8][40];
    __shared__ int   si[8][40];
    __shared__ int   bq[8][8];
    int w = threadIdx.x >> 5, lane = threadIdx.x & 31;
    int R = blockIdx.x*8 + w;
    int b = R / NROW;
    int ti = g_topi[R];
    if (ti < 0) { if (lane == 0) g_sgv[R] = 0; return; }
    size_t pbase = ((size_t)(b*NMM + ti)) * 40;
    for (int j = lane; j < 40; j += 32) { sv[w][j] = g_pv[pbase+j]; si[w][j] = g_pq[pbase+j]; }
    __syncwarp();
    if (lane == 0) {
        float fv[5]; int fq[5];
        #pragma unroll
        for (int j = 0; j < 5; j++) { fv[j] = -1e30f; fq[j] = 0x7fffffff; }
        for (int j = 0; j < 40; j++) {
            float v = sv[w][j]; int id = si[w][j];
            if (!(v < fv[4])) ins5(v, id, fv, fq);
        }
        int W = 0;
        #pragma unroll
        for (int mm = 0; mm < 5; mm++) {
            bool nb = fv[mm] > 0.0f;
            bq[w][mm] = nb ? fq[mm] : -1;
            W += nb ? 1 : 0;
        }
        bq[w][5] = W;
    }
    __syncwarp();
    int W = bq[w][5];
    if (W == 0) { if (lane == 0) g_sgv[R] = 0; return; }
    if (lane == 0) g_sgv[R] = 1;
    float invw = 1.0f / (1.0f + (float)W);
    int d0 = lane * 8;
    const float* mrow = g_matched + ((size_t)b*NMM + ti)*ND + d0;
    float acc[8];
    #pragma unroll
    for (int e = 0; e < 8; e++) acc[e] = mrow[e];
    #pragma unroll
    for (int mm = 0; mm < 5; mm++) {
        int q = bq[w][mm];
        if (q >= 0) {
            const float* ur = obj + ((size_t)b*NQ + q)*ND + d0;
            #pragma unroll
            for (int e = 0; e < 8; e++) acc[e] += ur[e];
        }
    }
    float* gr = g_gbar + (size_t)R*ND + d0;
    #pragma unroll
    for (int e = 0; e < 8; e++) gr[e] = acc[e] * invw;
}

// launch 8: focal loss over valid subgroups; 8 rows per block
__global__ __launch_bounds__(128) void focal_kernel(const float* __restrict__ Wc,
                                                    const float* __restrict__ bc) {
    int r0 = blockIdx.x * 8;
    int tid = threadIdx.x;
    __shared__ __align__(16) float4 gb4[8][ND/4];
    __shared__ int flags[8];
    if (tid < 8) flags[tid] = g_sgv[r0 + tid];
    for (int t = tid; t < 8*(ND/4); t += 128) {
        int rr = t >> 6, tt = t & 63;
        gb4[rr][tt] = ((const float4*)(g_gbar + (size_t)(r0+rr)*ND))[tt];
    }
    __syncthreads();
    int nv = flags[0]+flags[1]+flags[2]+flags[3]+flags[4]+flags[5]+flags[6]+flags[7];
    if (nv == 0) return;

    float fsum = 0.f;
    if (tid < NNC) {
        float xs[8];
        float bias = bc[tid];
        #pragma unroll
        for (int rr = 0; rr < 8; rr++) xs[rr] = bias;
        const float4* w4 = (const float4*)(Wc + (size_t)tid * ND);
        for (int t = 0; t < ND/4; t++) {
            float4 w = __ldg(w4 + t);
            #pragma unroll
            for (int rr = 0; rr < 8; rr++) {
                float4 g = gb4[rr][t];
                xs[rr] += w.x*g.x + w.y*g.y + w.z*g.z + w.w*g.w;
            }
        }
        #pragma unroll
        for (int rr = 0; rr < 8; rr++) {
            if (!flags[rr]) continue;
            float x = xs[rr];
            float fl;
            if (tid == NNC - 1) {
                float sp = (x < 0.f) ? (-x + log1pf(expf(x))) : log1pf(expf(-x));
                float sn = 1.f / (1.f + expf(x));
                fl = 0.25f * sp * sn * sn;
            } else {
                float sp = (x > 0.f) ? (x + log1pf(expf(-x))) : log1pf(expf(x));
                float sg = 1.f / (1.f + expf(-x));
                fl = 0.75f * sp * sg * sg;
            }
            fsum += fl;
        }
    }
    __shared__ float red[128];
    red[tid] = fsum;
    __syncthreads();
    for (int o = 64; o; o >>= 1) { if (tid < o) red[tid] += red[tid+o]; __syncthreads(); }
    if (tid == 0) {
        atomicAdd(&g_acc[0], (double)(red[0] / 91.0f));
        atomicAdd(&g_acc[1], (double)nv);
    }
}

// launch 9: column logsumexp of masked prototype-prototype similarities
__global__ void lseP_kernel(const float* __restrict__ protos) {
    int c = blockIdx.x;
    int tid = threadIdx.x;  // 128
    float val = -1e30f;
    if (tid < NCLS && tid != c) {
        const float4* a4 = (const float4*)(protos + (size_t)tid * ND);
        const float4* b4 = (const float4*)(protos + (size_t)c   * ND);
        float d = 0.f;
        for (int t = 0; t < ND/4; t++) {
            float4 a = __ldg(a4 + t), bb = __ldg(b4 + t);
            d += a.x*bb.x + a.y*bb.y + a.z*bb.z + a.w*bb.w;
        }
        val = d * g_pinv[tid] * g_pinv[c] / 0.1f;
    }
    __shared__ float sm[128];
    sm[tid] = val; __syncthreads();
    for (int o = 64; o; o >>= 1) { if (tid < o) sm[tid] = fmaxf(sm[tid], sm[tid+o]); __syncthreads(); }
    float mx = sm[0];
    __syncthreads();
    sm[tid] = (tid < NCLS && tid != c) ? expf(val - mx) : 0.f;
    __syncthreads();
    for (int o = 64; o; o >>= 1) { if (tid < o) sm[tid] += sm[tid+o]; __syncthreads(); }
    if (tid == 0) g_lseP[c] = mx + logf(sm[0]);
}

// launch 10: column logsumexp of masked sample-prototype similarities + combine with lseP
__global__ void lseS_kernel(const int* __restrict__ labels) {
    int c = blockIdx.x;
    int tid = threadIdx.x;  // 256
    float pin = g_pinv[c];
    float m = -1e30f, s = 0.f;
    for (int i = tid; i < NB*NMM; i += 256) {
        if (labels[i] == c) continue;
        float v = g_sims[(size_t)i*NCLS + c] * pin / 0.1f;
        if (v > m) { s = s * expf(m - v) + 1.f; m = v; }
        else       { s += expf(v - m); }
    }
    __shared__ float sm[256], ss[256];
    sm[tid] = m; ss[tid] = s;
    __syncthreads();
    for (int o = 128; o; o >>= 1) {
        if (tid < o) {
            float m2 = sm[tid+o], s2 = ss[tid+o];
            float M = fmaxf(sm[tid], m2);
            ss[tid] = ss[tid]*expf(sm[tid]-M) + s2*expf(m2-M);
            sm[tid] = M;
        }
        __syncthreads();
    }
    if (tid == 0) {
        float lse = sm[0] + logf(ss[0]);
        g_lseneg[c] = logaddexpf_(lse, g_lseP[c]);
    }
}

// launch 11
__global__ void cec_kernel(const int* __restrict__ labels) {
    int i = blockIdx.x * 256 + threadIdx.x;
    float term = 0.f;
    if (i < NB*NMM) {
        int l = labels[i];
        float pos = g_sims[(size_t)i*NCLS + l] * g_pinv[l] / 0.1f;
        term = -pos + logaddexpf_(pos, g_lseneg[l]);
    }
    __shared__ float sm[256];
    sm[threadIdx.x] = term;
    __syncthreads();
    for (int o = 128; o; o >>= 1) { if (threadIdx.x < o) sm[threadIdx.x] += sm[threadIdx.x+o]; __syncthreads(); }
    if (threadIdx.x == 0) atomicAdd(&g_acc[2], (double)sm[0]);
}

// launch 12
__global__ void finalize_kernel(float* out) {
    double ns = g_acc[1] < 1.0 ? 1.0 : g_acc[1];
    out[0] = (float)(g_acc[0] / ns);
    out[1] = (float)(g_acc[2] / (double)(NB*NMM));
}

// -------- launch --------
extern "C" void kernel_launch(void* const* d_in, const int* in_sizes, int n_in,
                              void* d_out, int out_size) {
    const float* obj    = (const float*)d_in[0];
    const float* protos = (const float*)d_in[1];
    const float* Wc     = (const float*)d_in[2];
    const float* bc     = (const float*)d_in[3];
    const int*   src    = (const int*)d_in[4];
    const int*   labels = (const int*)d_in[5];
    float* out = (float*)d_out;

    static int smem_set = 0;
    if (!smem_set) {
        cudaFuncSetAttribute(simbu_wmma_kernel,
                             cudaFuncAttributeMaxDynamicSharedMemorySize, 4*TILEB);
        smem_set = 1;
    }

    pack_obj_kernel<<<(NB*NQ*32 + 255)/256, 256>>>(obj);          // 1
    gather_pack_kernel<<<(NB*MPAD*32 + 255)/256, 256>>>(obj, src);// 2
    sims_kernel<<<(NB*NMM)/16, 256>>>(protos);                    // 3
    {
        dim3 grid(8, MPAD/128, NB);   // nTiles x mTiles(3) x batch
        simbu_wmma_kernel<<<grid, 256, 4*TILEB>>>();              // 4 <- profiled slot
    }
    topk_dists_kernel<<<NB*NCLS, 32>>>(labels);                   // 5
    pinv_kernel<<<NCLS, 32>>>(protos);                            // 6
    merge_gbar_kernel<<<(NB*NROW)/8, 256>>>(obj);                 // 7
    focal_kernel<<<(NB*NROW)/8, 128>>>(Wc, bc);                   // 8
    lseP_kernel<<<NCLS, 128>>>(protos);                           // 9
    lseS_kernel<<<NCLS, 256>>>(labels);                           // 10
    cec_kernel<<<(NB*NMM + 255)/256, 256>>>(labels);              // 11
    finalize_kernel<<<1, 1>>>(out);                               // 12
}

// round 7
// speedup vs baseline: 1.3704x; 1.0792x over previous
#include <cuda_runtime.h>
#include <cuda_bf16.h>
#include <mma.h>
#include <cstdint>
#include <math.h>

using namespace nvcuda;

#define NB   32
#define NQ   900
#define NMM  300
#define MPAD 384            // matched rows padded for 128-tiles
#define ND   256
#define NCLS 90
#define NNC  91
#define KB   5
#define NROW (NCLS*KB)      // 450 boundary rows per batch
#define NEGINF -1000000000.0f
#define SLD  72             // smem leading dim (bf16 elements), 144B rows
#define TILEB 18432u        // 128*72*2 bytes per tile

// -------- scratch (device globals; no allocation allowed) --------
__device__ __align__(128) float g_matched[NB*NMM*ND];     // gathered matched embeddings (raw)
__device__ __align__(128) float g_minv[NB*NMM];           // 1/||matched||
__device__ __align__(128) int   g_ism[NB*NQ];             // is-matched mask per (b,q)
__device__ __align__(128) float g_sims[NB*NMM*NCLS];      // matched_n . protos (fp32 exact)
__device__ __align__(128) float g_pinv[NCLS];             // 1/||proto||
__device__ __align__(128) int   g_topi[NB*NROW];          // top-K_B indices per (b,c,k), -1 invalid
__device__ __align__(128) __nv_bfloat16 g_Mh[NB*MPAD*ND]; // matched_n hi (padded rows zero)
__device__ __align__(128) __nv_bfloat16 g_Ml[NB*MPAD*ND]; // matched_n lo
__device__ __align__(128) __nv_bfloat16 g_Bh[NB*NQ*ND];   // obj_n hi
__device__ __align__(128) __nv_bfloat16 g_Bl[NB*NQ*ND];   // obj_n lo
__device__ __align__(128) int   g_pq[NB*NMM*8*KB];        // per-(matched row,nTile) top5 q candidates
__device__ __align__(128) float g_fv[NB*NMM*KB];          // exact top5 values per matched row
__device__ __align__(128) int   g_fq[NB*NMM*KB];          // exact top5 q per matched row
__device__ __align__(128) float g_gbar[NB*NROW*ND];       // subgroup means
__device__ __align__(128) int   g_sgv[NB*NROW];           // sg_valid
__device__ __align__(128) float g_lseP[NCLS];
__device__ __align__(128) float g_lseneg[NCLS];
__device__ double g_acc[3];   // 0: sum fl, 1: count sg_valid, 2: sum cec terms

// -------- helpers --------
__device__ __forceinline__ float logaddexpf_(float a, float b) {
    float m = fmaxf(a, b);
    return m + log1pf(expf(-fabsf(a - b)));
}

// insert (v,id) into sorted-desc top-5, tie -> lower id first (jax top_k semantics)
__device__ __forceinline__ void ins5(float v, int id, float* vals, int* ids) {
    #pragma unroll
    for (int j = 0; j < 5; j++) {
        bool better = (v > vals[j]) || (v == vals[j] && id < ids[j]);
        if (better) {
            float tv = vals[j]; int ti = ids[j];
            vals[j] = v; ids[j] = id;
            v = tv; id = ti;
        }
    }
}

__device__ __forceinline__ void split_bf16(float a, unsigned short& h, unsigned short& l) {
    __nv_bfloat16 hb = __float2bfloat16(a);
    float hf = __bfloat162float(hb);
    __nv_bfloat16 lb = __float2bfloat16(a - hf);
    h = __bfloat16_as_ushort(hb);
    l = __bfloat16_as_ushort(lb);
}

__device__ __forceinline__ void cp16(uint32_t s, const void* g) {
    asm volatile("cp.async.ca.shared.global [%0], [%1], 16;" :: "r"(s), "l"(g));
}
__device__ __forceinline__ void cp16z(uint32_t s, const void* g, int sz) {
    asm volatile("cp.async.ca.shared.global [%0], [%1], 16, %2;" :: "r"(s), "l"(g), "r"(sz));
}

// -------- kernels --------

// launch 1 (stream 0): one warp per obj row: normalize + bf16 hi/lo split + clear is_m (+ zero g_acc)
__global__ void pack_obj_kernel(const float* __restrict__ obj) {
    if (blockIdx.x == 0 && threadIdx.x < 3) g_acc[threadIdx.x] = 0.0;
    int warp = (blockIdx.x * blockDim.x + threadIdx.x) >> 5;
    int lane = threadIdx.x & 31;
    if (warp >= NB*NQ) return;
    const float4* r4 = (const float4*)(obj + (size_t)warp * ND);
    float4 a = r4[lane];
    float4 c = r4[lane + 32];
    float ss = a.x*a.x + a.y*a.y + a.z*a.z + a.w*a.w
             + c.x*c.x + c.y*c.y + c.z*c.z + c.w*c.w;
    #pragma unroll
    for (int o = 16; o; o >>= 1) ss += __shfl_xor_sync(0xffffffffu, ss, o);
    float inv = 1.0f / fmaxf(sqrtf(ss), 1e-12f);
    unsigned short h0,h1,h2,h3,l0,l1,l2,l3;
    uint2 hv, lv;
    split_bf16(a.x*inv,h0,l0); split_bf16(a.y*inv,h1,l1);
    split_bf16(a.z*inv,h2,l2); split_bf16(a.w*inv,h3,l3);
    hv.x = h0 | ((unsigned)h1<<16); hv.y = h2 | ((unsigned)h3<<16);
    lv.x = l0 | ((unsigned)l1<<16); lv.y = l2 | ((unsigned)l3<<16);
    ((uint2*)g_Bh)[(size_t)warp*64 + lane] = hv;
    ((uint2*)g_Bl)[(size_t)warp*64 + lane] = lv;
    split_bf16(c.x*inv,h0,l0); split_bf16(c.y*inv,h1,l1);
    split_bf16(c.z*inv,h2,l2); split_bf16(c.w*inv,h3,l3);
    hv.x = h0 | ((unsigned)h1<<16); hv.y = h2 | ((unsigned)h3<<16);
    lv.x = l0 | ((unsigned)l1<<16); lv.y = l2 | ((unsigned)l3<<16);
    ((uint2*)g_Bh)[(size_t)warp*64 + lane + 32] = hv;
    ((uint2*)g_Bl)[(size_t)warp*64 + lane + 32] = lv;
    if (lane == 0) g_ism[warp] = 0;
}

// launch 2 (stream 0): one warp per padded matched row: gather + norm + is_m + fp32 copy + bf16 hi/lo
__global__ void gather_pack_kernel(const float* __restrict__ obj, const int* __restrict__ src) {
    int warp = (blockIdx.x * blockDim.x + threadIdx.x) >> 5;
    int lane = threadIdx.x & 31;
    if (warp >= NB*MPAD) return;
    int b = warp / MPAD, n = warp - b*MPAD;
    size_t mrow = (size_t)b*MPAD + n;
    if (n >= NMM) {
        uint2 z = make_uint2(0,0);
        ((uint2*)g_Mh)[mrow*64 + lane] = z;
        ((uint2*)g_Mh)[mrow*64 + lane + 32] = z;
        ((uint2*)g_Ml)[mrow*64 + lane] = z;
        ((uint2*)g_Ml)[mrow*64 + lane + 32] = z;
        return;
    }
    int idx = src[b*NMM + n];
    const float4* r4 = (const float4*)(obj + ((size_t)b*NQ + idx) * ND);
    float4 a = r4[lane];
    float4 c = r4[lane + 32];
    float4* o4 = (float4*)(g_matched + ((size_t)b*NMM + n) * ND);
    o4[lane] = a; o4[lane + 32] = c;
    float ss = a.x*a.x + a.y*a.y + a.z*a.z + a.w*a.w
             + c.x*c.x + c.y*c.y + c.z*c.z + c.w*c.w;
    #pragma unroll
    for (int o = 16; o; o >>= 1) ss += __shfl_xor_sync(0xffffffffu, ss, o);
    float inv = 1.0f / fmaxf(sqrtf(ss), 1e-12f);
    unsigned short h0,h1,h2,h3,l0,l1,l2,l3;
    uint2 hv, lv;
    split_bf16(a.x*inv,h0,l0); split_bf16(a.y*inv,h1,l1);
    split_bf16(a.z*inv,h2,l2); split_bf16(a.w*inv,h3,l3);
    hv.x = h0 | ((unsigned)h1<<16); hv.y = h2 | ((unsigned)h3<<16);
    lv.x = l0 | ((unsigned)l1<<16); lv.y = l2 | ((unsigned)l3<<16);
    ((uint2*)g_Mh)[mrow*64 + lane] = hv;
    ((uint2*)g_Ml)[mrow*64 + lane] = lv;
    split_bf16(c.x*inv,h0,l0); split_bf16(c.y*inv,h1,l1);
    split_bf16(c.z*inv,h2,l2); split_bf16(c.w*inv,h3,l3);
    hv.x = h0 | ((unsigned)h1<<16); hv.y = h2 | ((unsigned)h3<<16);
    lv.x = l0 | ((unsigned)l1<<16); lv.y = l2 | ((unsigned)l3<<16);
    ((uint2*)g_Mh)[mrow*64 + lane + 32] = hv;
    ((uint2*)g_Ml)[mrow*64 + lane + 32] = lv;
    if (lane == 0) {
        g_minv[b*NMM + n] = inv;
        g_ism[b*NQ + idx] = 1;
    }
}

// launch 3 (stream 2): sims[r, c] = minv[r] * (matched[r] . protos[c]) ; fp32 exact
__global__ __launch_bounds__(256) void sims_kernel(const float* __restrict__ protos) {
    __shared__ __align__(16) float As[16*ND];
    __shared__ float sminv[16];
    int r0 = blockIdx.x * 16;
    int tid = threadIdx.x;
    float4* s4 = (float4*)As;
    const float4* gm4 = (const float4*)(g_matched + (size_t)r0 * ND);
    for (int i = tid; i < 16*ND/4; i += 256) s4[i] = gm4[i];
    if (tid < 16) sminv[tid] = g_minv[r0 + tid];
    __syncthreads();
    for (int o = tid; o < 16*NCLS; o += 256) {
        int r = o / NCLS;
        int c = o - r*NCLS;
        const float4* p4 = (const float4*)(protos + (size_t)c * ND);
        const float4* a4 = (const float4*)(As + r * ND);
        float acc = 0.f;
        #pragma unroll 8
        for (int t = 0; t < ND/4; t++) {
            float4 a = a4[t];
            float4 p = __ldg(p4 + t);
            acc += a.x*p.x + a.y*p.y + a.z*p.z + a.w*p.w;
        }
        g_sims[(size_t)(r0 + r)*NCLS + c] = acc * sminv[r];
    }
}

// launch 4 (stream 0, PROFILED SLOT): S = matched_n @ obj_n^T via WMMA bf16 3-term hi/lo,
// cp.async double-buffered, fused per-row-per-ntile top-5 candidate epilogue (indices only).
__global__ __launch_bounds__(256) void simbu_wmma_kernel() {
    extern __shared__ __align__(16) char dsm[];   // 4 tiles of TILEB: [A0,B0,A1,B1]
    __shared__ int smask[128];
    int tid = threadIdx.x, wid = tid >> 5, lane = tid & 31;
    int nT = blockIdx.x, mT = blockIdx.y, b = blockIdx.z;
    const int mBase = mT*128, nBase = nT*128;
    uint32_t sbase = (uint32_t)__cvta_generic_to_shared(dsm);

    if (tid < 128) {
        int n = nBase + tid;
        smask[tid] = (n < NQ) ? g_ism[b*NQ + n] : 2;
    }

    wmma::fragment<wmma::accumulator, 16, 16, 16, float> acc[8];
    #pragma unroll
    for (int i = 0; i < 8; i++) wmma::fill_fragment(acc[i], 0.0f);

    #define ISSUE_CHUNK(chunk) do {                                                   \
        int seg_ = (chunk) >> 2, kc_ = (chunk) & 3, bi_ = (chunk) & 1;                \
        const __nv_bfloat16* Asrc_ = (seg_ == 1) ? g_Ml : g_Mh;                       \
        const __nv_bfloat16* Bsrc_ = (seg_ == 2) ? g_Bl : g_Bh;                       \
        uint32_t sa_ = sbase + (uint32_t)bi_ * (2u*TILEB);                            \
        uint32_t sb_ = sa_ + TILEB;                                                   \
        _Pragma("unroll")                                                             \
        for (int i_ = 0; i_ < 2; i_++) {                                              \
            int e_ = i_*256 + tid;                                                    \
            int r_ = e_ >> 2, g_ = e_ & 3;                                            \
            cp16(sa_ + (uint32_t)(r_*144 + g_*16),                                    \
                 Asrc_ + ((size_t)(b*MPAD + mBase + r_)*ND + kc_*64 + g_*8));         \
            int br_ = nBase + r_;                                                     \
            cp16z(sb_ + (uint32_t)(r_*144 + g_*16),                                   \
                  Bsrc_ + ((size_t)b*NQ + (br_ < NQ ? br_ : 0))*ND + kc_*64 + g_*8,   \
                  (br_ < NQ) ? 16 : 0);                                               \
        }                                                                             \
        asm volatile("cp.async.commit_group;" ::: "memory");                          \
    } while (0)

    ISSUE_CHUNK(0);
    for (int c = 0; c < 12; c++) {
        if (c + 1 < 12) {
            ISSUE_CHUNK(c + 1);
            asm volatile("cp.async.wait_group 1;" ::: "memory");
        } else {
            asm volatile("cp.async.wait_group 0;" ::: "memory");
        }
        __syncthreads();
        int bi = c & 1;
        const __nv_bfloat16* Ab = (const __nv_bfloat16*)(dsm + (size_t)bi*(2*TILEB));
        const __nv_bfloat16* Bb = (const __nv_bfloat16*)(dsm + (size_t)bi*(2*TILEB) + TILEB);
        #pragma unroll
        for (int ks = 0; ks < 4; ks++) {
            wmma::fragment<wmma::matrix_a, 16, 16, 16, __nv_bfloat16, wmma::row_major> af;
            wmma::load_matrix_sync(af, Ab + (wid*16)*SLD + ks*16, SLD);
            #pragma unroll
            for (int nt = 0; nt < 8; nt++) {
                wmma::fragment<wmma::matrix_b, 16, 16, 16, __nv_bfloat16, wmma::col_major> bf;
                wmma::load_matrix_sync(bf, Bb + (nt*16)*SLD + ks*16, SLD);
                wmma::mma_sync(acc[nt], af, bf, acc[nt]);
            }
        }
        __syncthreads();
    }
    #undef ISSUE_CHUNK

    // epilogue: per-warp 16x20 f32 staging buffer aliased over buffer 0
    float* ebuf = reinterpret_cast<float*>(dsm) + (size_t)wid * 320;
    float tv[5]; int tq[5];
    #pragma unroll
    for (int j = 0; j < 5; j++) { tv[j] = -1e30f; tq[j] = 0x7fffffff; }
    #pragma unroll
    for (int nt = 0; nt < 8; nt++) {
        wmma::store_matrix_sync(ebuf, acc[nt], 20, wmma::mem_row_major);
        __syncwarp();
        if (lane < 16) {
            #pragma unroll
            for (int cc = 0; cc < 16; cc++) {
                int col = nt*16 + cc;
                int mk = smask[col];
                float v; int id;
                if (mk == 2)      { v = -1e30f; id = 0x7fffffff; }
                else if (mk == 1) { v = NEGINF; id = nBase + col; }
                else              { v = ebuf[lane*20 + cc]; id = nBase + col; }
                ins5(v, id, tv, tq);
            }
        }
        __syncwarp();
    }
    if (lane < 16) {
        int m = mBase + wid*16 + lane;
        if (m < NMM) {
            size_t base = ((size_t)(b*NMM + m)*8 + nT)*5;
            #pragma unroll
            for (int j = 0; j < 5; j++) g_pq[base+j] = tq[j];
        }
    }
}

// launch 5 (stream 0): exact fp32 rerank of 40 candidates per matched row -> final top-5
__global__ __launch_bounds__(256) void rerank_kernel(const float* __restrict__ obj) {
    int warp = (blockIdx.x * blockDim.x + threadIdx.x) >> 5;
    int lane = threadIdx.x & 31;
    if (warp >= NB*NMM) return;
    int b = warp / NMM;
    float minv = g_minv[warp];
    const float4* mr = (const float4*)(g_matched + (size_t)warp * ND);
    float4 m0 = mr[lane*2], m1 = mr[lane*2 + 1];
    float fv[5]; int fq[5];
    #pragma unroll
    for (int j = 0; j < 5; j++) { fv[j] = -1e30f; fq[j] = 0x7fffffff; }
    size_t pbase = (size_t)warp * 40;
    for (int j = 0; j < 40; j++) {
        int q = g_pq[pbase + j];
        if (q == 0x7fffffff) continue;
        if (g_ism[b*NQ + q]) continue;      // masked (NEGINF) candidates stay excluded
        const float4* ur = (const float4*)(obj + ((size_t)b*NQ + q) * ND);
        float4 u0 = ur[lane*2], u1 = ur[lane*2 + 1];
        float dot = m0.x*u0.x + m0.y*u0.y + m0.z*u0.z + m0.w*u0.w
                  + m1.x*u1.x + m1.y*u1.y + m1.z*u1.z + m1.w*u1.w;
        float nsq = u0.x*u0.x + u0.y*u0.y + u0.z*u0.z + u0.w*u0.w
                  + u1.x*u1.x + u1.y*u1.y + u1.z*u1.z + u1.w*u1.w;
        #pragma unroll
        for (int o = 16; o; o >>= 1) {
            dot += __shfl_xor_sync(0xffffffffu, dot, o);
            nsq += __shfl_xor_sync(0xffffffffu, nsq, o);
        }
        float sim = dot * minv / fmaxf(sqrtf(nsq), 1e-12f);
        ins5(sim, q, fv, fq);
    }
    if (lane == 0) {
        #pragma unroll
        for (int j = 0; j < 5; j++) {
            g_fv[(size_t)warp*5 + j] = fv[j];
            g_fq[(size_t)warp*5 + j] = fq[j];
        }
    }
}

// launch 6 (stream 2): per (b,c): top-5 of dist = 1 - sim over n with label==c
__global__ void topk_dists_kernel(const int* __restrict__ labels) {
    int bc = blockIdx.x;
    int b = bc / NCLS, c = bc - b*NCLS;
    int lane = threadIdx.x;
    float lv[5]; int li[5];
    #pragma unroll
    for (int j = 0; j < 5; j++) { lv[j] = -1e30f; li[j] = 0x7fffffff; }
    int cnt = 0;
    for (int n = lane; n < NMM; n += 32) {
        if (labels[b*NMM + n] == c) {
            cnt++;
            float dd = 1.0f - g_sims[(size_t)(b*NMM + n)*NCLS + c];
            ins5(dd, n, lv, li);
        }
    }
    #pragma unroll
    for (int o = 16; o; o >>= 1) cnt += __shfl_xor_sync(0xffffffffu, cnt, o);
    __shared__ float sv[160];
    __shared__ int   si[160];
    #pragma unroll
    for (int j = 0; j < 5; j++) { sv[lane*5 + j] = lv[j]; si[lane*5 + j] = li[j]; }
    __syncwarp();
    if (lane == 0) {
        float fv[5]; int fi[5];
        #pragma unroll
        for (int j = 0; j < 5; j++) { fv[j] = -1e30f; fi[j] = 0x7fffffff; }
        for (int t = 0; t < 160; t++)
            if (si[t] != 0x7fffffff) ins5(sv[t], si[t], fv, fi);
        #pragma unroll
        for (int k = 0; k < 5; k++)
            g_topi[(size_t)bc*KB + k] = (k < cnt) ? fi[k] : -1;
    }
}

// launch 7 (stream 2)
__global__ void pinv_kernel(const float* __restrict__ protos) {
    int c = blockIdx.x;
    int lane = threadIdx.x;
    const float4* r4 = (const float4*)(protos + (size_t)c * ND);
    float ss = 0.f;
    for (int t = lane; t < ND/4; t += 32) {
        float4 v = r4[t];
        ss += v.x*v.x + v.y*v.y + v.z*v.z + v.w*v.w;
    }
    #pragma unroll
    for (int o = 16; o; o >>= 1) ss += __shfl_xor_sync(0xffffffffu, ss, o);
    if (lane == 0) g_pinv[c] = 1.0f / fmaxf(sqrtf(ss), 1e-6f);
}

// launch 8 (stream 2): column logsumexp of masked prototype-prototype similarities
__global__ void lseP_kernel(const float* __restrict__ protos) {
    int c = blockIdx.x;
    int tid = threadIdx.x;  // 128
    float val = -1e30f;
    if (tid < NCLS && tid != c) {
        const float4* a4 = (const float4*)(protos + (size_t)tid * ND);
        const float4* b4 = (const float4*)(protos + (size_t)c   * ND);
        float d = 0.f;
        for (int t = 0; t < ND/4; t++) {
            float4 a = __ldg(a4 + t), bb = __ldg(b4 + t);
            d += a.x*bb.x + a.y*bb.y + a.z*bb.z + a.w*bb.w;
        }
        val = d * g_pinv[tid] * g_pinv[c] / 0.1f;
    }
    __shared__ float sm[128];
    sm[tid] = val; __syncthreads();
    for (int o = 64; o; o >>= 1) { if (tid < o) sm[tid] = fmaxf(sm[tid], sm[tid+o]); __syncthreads(); }
    float mx = sm[0];
    __syncthreads();
    sm[tid] = (tid < NCLS && tid != c) ? expf(val - mx) : 0.f;
    __syncthreads();
    for (int o = 64; o; o >>= 1) { if (tid < o) sm[tid] += sm[tid+o]; __syncthreads(); }
    if (tid == 0) g_lseP[c] = mx + logf(sm[0]);
}

// launch 9 (stream 2): column logsumexp of masked sample-prototype sims + combine
__global__ void lseS_kernel(const int* __restrict__ labels) {
    int c = blockIdx.x;
    int tid = threadIdx.x;  // 256
    float pin = g_pinv[c];
    float m = -1e30f, s = 0.f;
    for (int i = tid; i < NB*NMM; i += 256) {
        if (labels[i] == c) continue;
        float v = g_sims[(size_t)i*NCLS + c] * pin / 0.1f;
        if (v > m) { s = s * expf(m - v) + 1.f; m = v; }
        else       { s += expf(v - m); }
    }
    __shared__ float sm[256], ss[256];
    sm[tid] = m; ss[tid] = s;
    __syncthreads();
    for (int o = 128; o; o >>= 1) {
        if (tid < o) {
            float m2 = sm[tid+o], s2 = ss[tid+o];
            float M = fmaxf(sm[tid], m2);
            ss[tid] = ss[tid]*expf(sm[tid]-M) + s2*expf(m2-M);
            sm[tid] = M;
        }
        __syncthreads();
    }
    if (tid == 0) {
        float lse = sm[0] + logf(ss[0]);
        g_lseneg[c] = logaddexpf_(lse, g_lseP[c]);
    }
}

// launch 10 (stream 2)
__global__ void cec_kernel(const int* __restrict__ labels) {
    int i = blockIdx.x * 256 + threadIdx.x;
    float term = 0.f;
    if (i < NB*NMM) {
        int l = labels[i];
        float pos = g_sims[(size_t)i*NCLS + l] * g_pinv[l] / 0.1f;
        term = -pos + logaddexpf_(pos, g_lseneg[l]);
    }
    __shared__ float sm[256];
    sm[threadIdx.x] = term;
    __syncthreads();
    for (int o = 128; o; o >>= 1) { if (threadIdx.x < o) sm[threadIdx.x] += sm[threadIdx.x+o]; __syncthreads(); }
    if (threadIdx.x == 0) atomicAdd(&g_acc[2], (double)sm[0]);
}

// launch 11 (stream 0, after join): per boundary row: read exact top-5 -> g_bar + sg_valid
__global__ __launch_bounds__(256) void merge_gbar_kernel(const float* __restrict__ obj) {
    __shared__ int bq[8][8];
    int w = threadIdx.x >> 5, lane = threadIdx.x & 31;
    int R = blockIdx.x*8 + w;
    int b = R / NROW;
    int ti = g_topi[R];
    if (ti < 0) { if (lane == 0) g_sgv[R] = 0; return; }
    size_t fb = ((size_t)(b*NMM + ti))*5;
    if (lane == 0) {
        int W = 0;
        #pragma unroll
        for (int mm = 0; mm < 5; mm++) {
            float v = g_fv[fb + mm];
            bool nb = v > 0.0f;
            bq[w][mm] = nb ? g_fq[fb + mm] : -1;
            W += nb ? 1 : 0;
        }
        bq[w][5] = W;
    }
    __syncwarp();
    int W = bq[w][5];
    if (W == 0) { if (lane == 0) g_sgv[R] = 0; return; }
    if (lane == 0) g_sgv[R] = 1;
    float invw = 1.0f / (1.0f + (float)W);
    int d0 = lane * 8;
    const float* mrow = g_matched + ((size_t)b*NMM + ti)*ND + d0;
    float acc[8];
    #pragma unroll
    for (int e = 0; e < 8; e++) acc[e] = mrow[e];
    #pragma unroll
    for (int mm = 0; mm < 5; mm++) {
        int q = bq[w][mm];
        if (q >= 0) {
            const float* ur = obj + ((size_t)b*NQ + q)*ND + d0;
            #pragma unroll
            for (int e = 0; e < 8; e++) acc[e] += ur[e];
        }
    }
    float* gr = g_gbar + (size_t)R*ND + d0;
    #pragma unroll
    for (int e = 0; e < 8; e++) gr[e] = acc[e] * invw;
}

// launch 12 (stream 0): focal loss over valid subgroups; 8 rows per block
__global__ __launch_bounds__(128) void focal_kernel(const float* __restrict__ Wc,
                                                    const float* __restrict__ bc) {
    int r0 = blockIdx.x * 8;
    int tid = threadIdx.x;
    __shared__ __align__(16) float4 gb4[8][ND/4];
    __shared__ int flags[8];
    if (tid < 8) flags[tid] = g_sgv[r0 + tid];
    for (int t = tid; t < 8*(ND/4); t += 128) {
        int rr = t >> 6, tt = t & 63;
        gb4[rr][tt] = ((const float4*)(g_gbar + (size_t)(r0+rr)*ND))[tt];
    }
    __syncthreads();
    int nv = flags[0]+flags[1]+flags[2]+flags[3]+flags[4]+flags[5]+flags[6]+flags[7];
    if (nv == 0) return;

    float fsum = 0.f;
    if (tid < NNC) {
        float xs[8];
        float bias = bc[tid];
        #pragma unroll
        for (int rr = 0; rr < 8; rr++) xs[rr] = bias;
        const float4* w4 = (const float4*)(Wc + (size_t)tid * ND);
        for (int t = 0; t < ND/4; t++) {
            float4 w = __ldg(w4 + t);
            #pragma unroll
            for (int rr = 0; rr < 8; rr++) {
                float4 g = gb4[rr][t];
                xs[rr] += w.x*g.x + w.y*g.y + w.z*g.z + w.w*g.w;
            }
        }
        #pragma unroll
        for (int rr = 0; rr < 8; rr++) {
            if (!flags[rr]) continue;
            float x = xs[rr];
            float fl;
            if (tid == NNC - 1) {
                float sp = (x < 0.f) ? (-x + log1pf(expf(x))) : log1pf(expf(-x));
                float sn = 1.f / (1.f + expf(x));
                fl = 0.25f * sp * sn * sn;
            } else {
                float sp = (x > 0.f) ? (x + log1pf(expf(-x))) : log1pf(expf(x));
                float sg = 1.f / (1.f + expf(-x));
                fl = 0.75f * sp * sg * sg;
            }
            fsum += fl;
        }
    }
    __shared__ float red[128];
    red[tid] = fsum;
    __syncthreads();
    for (int o = 64; o; o >>= 1) { if (tid < o) red[tid] += red[tid+o]; __syncthreads(); }
    if (tid == 0) {
        atomicAdd(&g_acc[0], (double)(red[0] / 91.0f));
        atomicAdd(&g_acc[1], (double)nv);
    }
}

// launch 13 (stream 0)
__global__ void finalize_kernel(float* out) {
    double ns = g_acc[1] < 1.0 ? 1.0 : g_acc[1];
    out[0] = (float)(g_acc[0] / ns);
    out[1] = (float)(g_acc[2] / (double)(NB*NMM));
}

// -------- launch --------
extern "C" void kernel_launch(void* const* d_in, const int* in_sizes, int n_in,
                              void* d_out, int out_size) {
    const float* obj    = (const float*)d_in[0];
    const float* protos = (const float*)d_in[1];
    const float* Wc     = (const float*)d_in[2];
    const float* bc     = (const float*)d_in[3];
    const int*   src    = (const int*)d_in[4];
    const int*   labels = (const int*)d_in[5];
    float* out = (float*)d_out;

    static cudaStream_t s2 = 0;
    static cudaEvent_t ev0 = 0, ev1 = 0;
    if (!s2) {
        cudaStreamCreateWithFlags(&s2, cudaStreamNonBlocking);
        cudaEventCreateWithFlags(&ev0, cudaEventDisableTiming);
        cudaEventCreateWithFlags(&ev1, cudaEventDisableTiming);
        cudaFuncSetAttribute(simbu_wmma_kernel,
                             cudaFuncAttributeMaxDynamicSharedMemorySize, 4*TILEB);
    }

    // stream 0: shared prologue
    pack_obj_kernel<<<(NB*NQ*32 + 255)/256, 256>>>(obj);            // 1
    gather_pack_kernel<<<(NB*MPAD*32 + 255)/256, 256>>>(obj, src);  // 2

    // fork: s2 runs the sims/lse chain under the GEMM
    cudaEventRecord(ev0, 0);
    cudaStreamWaitEvent(s2, ev0, 0);

    sims_kernel<<<(NB*NMM)/16, 256, 0, s2>>>(protos);               // 3 (s2)
    {
        dim3 grid(8, MPAD/128, NB);
        simbu_wmma_kernel<<<grid, 256, 4*TILEB>>>();                // 4 (s0, profiled)
    }
    rerank_kernel<<<(NB*NMM*32 + 255)/256, 256>>>(obj);             // 5 (s0)
    topk_dists_kernel<<<NB*NCLS, 32, 0, s2>>>(labels);              // 6 (s2)
    pinv_kernel<<<NCLS, 32, 0, s2>>>(protos);                       // 7 (s2)
    lseP_kernel<<<NCLS, 128, 0, s2>>>(protos);                      // 8 (s2)
    lseS_kernel<<<NCLS, 256, 0, s2>>>(labels);                      // 9 (s2)
    cec_kernel<<<(NB*NMM + 255)/256, 256, 0, s2>>>(labels);         // 10 (s2)

    // join
    cudaEventRecord(ev1, s2);
    cudaStreamWaitEvent(0, ev1, 0);

    merge_gbar_kernel<<<(NB*NROW)/8, 256>>>(obj);                   // 11 (s0)
    focal_kernel<<<(NB*NROW)/8, 128>>>(Wc, bc);                     // 12 (s0)
    finalize_kernel<<<1, 1>>>(out);                                 // 13 (s0)
}